// round 12
// baseline (speedup 1.0000x reference)
#include <cuda_runtime.h>
#include <cstdint>

// ---------------------------------------------------------------------------
// MPS amplitude contraction, segment-table approach (v12 = v11 + chunk fix).
// amplitude(s) = left[x0] . B[x1] ... B[x62] . right[x63]   (complex, D=16)
//
// Split: Lvec covers x0..x13, 6 x Seg6 cover x14..x49, Rvec covers x50..x63.
// 6-bit binning (key = x14..x19) fused into the pack kernel -> warps in
// k_main have uniform stage-1 segment idx -> rotated LDS.128 dedups 4
// wavefronts to 1. Overflow spills to a catch-all region processed unsorted.
// Pipeline: nop -> k1(pack+bin || Seg6) -> k2(tables + cursor snapshot) ->
// k_main.  v12 fix: per-block slot chunk is a multiple of 32 (960), so warp
// chunks never straddle a bin boundary (SLOTCAP = 68*32).
// ---------------------------------------------------------------------------

typedef unsigned long long ull;

#define NBIN     64
#define SLOTCAP  2176                 // 68 * 32
#define MAIN_SLOTS (NBIN * SLOTCAP)   // 139264
#define OV_BASE  MAIN_SLOTS
#define CHUNK    960                  // 30 * 32; 148*960 = 142080 >= MAIN_SLOTS

__device__ float2 g_seg [64 * 256];
__device__ float2 g_lv8 [256 * 16];
__device__ float2 g_rv8 [256 * 16];
__device__ float2 g_lvec[16384 * 16];
__device__ float2 g_rvec[16384 * 16];
__device__ ulonglong2 g_xs[MAIN_SLOTS + 131072];  // {packed, orig}
__device__ int g_cur[NBIN + 1];       // bin cursors (zero-init; k2 re-zeroes)
__device__ int g_binCount[NBIN + 1];

// ---- packed fp32x2 helpers ----
__device__ __forceinline__ ull pack2(float lo, float hi) {
    ull r; asm("mov.b64 %0, {%1,%2};" : "=l"(r) : "f"(lo), "f"(hi)); return r;
}
__device__ __forceinline__ void unpack2(ull v, float& lo, float& hi) {
    asm("mov.b64 {%0,%1}, %2;" : "=f"(lo), "=f"(hi) : "l"(v));
}
__device__ __forceinline__ ull ffma2(ull a, ull b, ull c) {
    ull d; asm("fma.rn.f32x2 %0, %1, %2, %3;" : "=l"(d) : "l"(a), "l"(b), "l"(c));
    return d;
}
__device__ __forceinline__ void lds128(unsigned addr, ull& p0, ull& p1) {
    asm volatile("ld.shared.v2.b64 {%0,%1}, [%2];" : "=l"(p0), "=l"(p1) : "r"(addr));
}
__device__ __forceinline__ void sts128(unsigned addr, ull p0, ull p1) {
    asm volatile("st.shared.v2.b64 [%0], {%1,%2};" :: "r"(addr), "l"(p0), "l"(p1));
}
__device__ __forceinline__ void ldg128(const void* p, ull& p0, ull& p1) {
    asm volatile("ld.global.nc.v2.b64 {%0,%1}, [%2];" : "=l"(p0), "=l"(p1) : "l"(p));
}

// scalar complex fma: (rr,ri) += (ax+i ay) * (bx+i by)
__device__ __forceinline__ void cfma(float& rr, float& ri, float ax, float ay,
                                     float bx, float by) {
    rr = fmaf(ax, bx, rr);
    rr = fmaf(-ay, by, rr);
    ri = fmaf(ax, by, ri);
    ri = fmaf(ay, bx, ri);
}

// 16x16 complex matmul, one output element per thread (e = i*16+k, 256 thr)
__device__ __forceinline__ void mm16(const float2* A, const float2* Bm,
                                     float2* C, int e) {
    int i = e >> 4, k = e & 15;
    float xr0 = 0.f, xi0 = 0.f, xr1 = 0.f, xi1 = 0.f;
#pragma unroll
    for (int j = 0; j < 16; j += 2) {
        float2 a0 = A[(i << 4) + j],     b0 = Bm[(j << 4) + k];
        float2 a1 = A[(i << 4) + j + 1], b1 = Bm[((j + 1) << 4) + k];
        cfma(xr0, xi0, a0.x, a0.y, b0.x, b0.y);
        cfma(xr1, xi1, a1.x, a1.y, b1.x, b1.y);
    }
    C[e] = make_float2(xr0 + xr1, xi0 + xi1);
}

__global__ void k_nop() {}

// ---------------------------------------------------------------------------
// k1: 320 blocks x 512 threads.
// Blocks 0..255: pack 512 samples (16 warps x 32, warp-ballot) and scatter
//   {packed, orig} into bin (x14..x19) at atomic cursor position; overflow
//   goes to the catch-all region (correct for any placement).
// Blocks 256..319: build Seg6[c] (parallel Seg3 trees) + Lv8/Rv8 slices.
// ---------------------------------------------------------------------------
__global__ __launch_bounds__(512) void k1(
        const int* __restrict__ x, int N,
        const float* __restrict__ br_, const float* __restrict__ bi_,
        const float* __restrict__ lr_, const float* __restrict__ li_,
        const float* __restrict__ rr_, const float* __restrict__ ri_) {
    if (blockIdx.x < 256) {
        int W = (blockIdx.x << 4) + (threadIdx.x >> 5);
        int lane = threadIdx.x & 31;
        int s0 = W << 5;
        if (s0 >= N) return;
        ull mine = 0;
#pragma unroll 4
        for (int q = 0; q < 32; q++) {
            size_t base = (size_t)(s0 + q) << 6;
            unsigned b0 = __ballot_sync(0xFFFFFFFFu, x[base + lane] & 1);
            unsigned b1 = __ballot_sync(0xFFFFFFFFu, x[base + 32 + lane] & 1);
            ull packed = ((ull)__brev(b0) << 32) | (ull)__brev(b1);
            if (lane == q) mine = packed;
        }
        int s = s0 + lane;
        if (s < N) {
            unsigned key = (unsigned)(mine >> 44) & 63u;   // x14..x19
            int pos = atomicAdd(&g_cur[key], 1);
            int slot;
            if (pos < SLOTCAP) slot = (int)key * SLOTCAP + pos;
            else               slot = OV_BASE + atomicAdd(&g_cur[NBIN], 1);
            g_xs[slot] = make_ulonglong2(mine, (ull)(unsigned)s);
        }
        return;
    }

    // ---- Seg6 builder blocks ----
    __shared__ float2 sB[512], sT[2][256], sP[2][256], sS6[256];
    __shared__ float2 sLv2[64], sRv2[64];
    __shared__ float sLr[32], sLi[32], sRr[32], sRi[32];
    int e = threadIdx.x, c = blockIdx.x - 256;
    int half = e >> 8, e2 = e & 255;

    sB[e] = make_float2(br_[e], bi_[e]);
    if (e < 32) { sLr[e] = lr_[e]; sLi[e] = li_[e]; sRr[e] = rr_[e]; sRi[e] = ri_[e]; }
    __syncthreads();

    int a = c >> 3, b = c & 7;
    int v = half ? b : a;
    mm16(sB + (((v >> 1) & 1) << 8), sB + ((v & 1) << 8), sT[half], e2);
    __syncthreads();
    mm16(sB + ((v >> 2) << 8), sT[half], sP[half], e2);
    __syncthreads();
    if (half == 0) mm16(sP[0], sP[1], sS6, e2);   // Seg6[c] = Seg3[a].Seg3[b]
    __syncthreads();

    if (half == 0) g_seg[(c << 8) + e2] = sS6[e2];

    if (e < 64) {  // Lv2[(s<<1)|bb][k]
        int vv = e >> 4, k = e & 15, sgn = vv >> 1, bb = vv & 1;
        float xr = 0.f, xi = 0.f;
#pragma unroll
        for (int j = 0; j < 16; j++) {
            float2 m = sB[(bb << 8) + (j << 4) + k];
            cfma(xr, xi, sLr[sgn * 16 + j], sLi[sgn * 16 + j], m.x, m.y);
        }
        sLv2[e] = make_float2(xr, xi);
    } else if (e < 128) {  // Rv2[(bb<<1)|r][i]
        int t2 = e - 64, vv = t2 >> 4, i = t2 & 15, bb = vv >> 1, r = vv & 1;
        float xr = 0.f, xi = 0.f;
#pragma unroll
        for (int j = 0; j < 16; j++) {
            float2 m = sB[(bb << 8) + (i << 4) + j];
            cfma(xr, xi, m.x, m.y, sRr[r * 16 + j], sRi[r * 16 + j]);
        }
        sRv2[t2] = make_float2(xr, xi);
    }
    __syncthreads();

    if (e < 64) {  // Lv8[(a2<<6)|c][k]
        int a2 = e >> 4, k = e & 15;
        float xr = 0.f, xi = 0.f;
#pragma unroll
        for (int j = 0; j < 16; j++) {
            float2 o = sLv2[(a2 << 4) + j];
            float2 m = sS6[(j << 4) + k];
            cfma(xr, xi, o.x, o.y, m.x, m.y);
        }
        g_lv8[(((a2 << 6) | c) << 4) + k] = make_float2(xr, xi);
    } else if (e < 128) {  // Rv8[(c<<2)|b2][i]
        int t2 = e - 64, b2 = t2 >> 4, i = t2 & 15;
        float xr = 0.f, xi = 0.f;
#pragma unroll
        for (int j = 0; j < 16; j++) {
            float2 m = sS6[(i << 4) + j];
            float2 w = sRv2[(b2 << 4) + j];
            cfma(xr, xi, m.x, m.y, w.x, w.y);
        }
        g_rv8[(((c << 2) | b2) << 4) + i] = make_float2(xr, xi);
    }
}

// ---------------------------------------------------------------------------
// k2: 256 blocks x 256 threads. Table expansion (split p-ranges).
// Block 0 additionally snapshots bin cursors -> g_binCount and zeroes them
// for the next replay (zero-init covers the very first call).
// ---------------------------------------------------------------------------
__global__ void k2() {
    __shared__ float2 S[256];
    int blk = blockIdx.x;
    int t = threadIdx.x;

    if (blk == 0 && t <= NBIN) {
        g_binCount[t] = g_cur[t];
        g_cur[t] = 0;
    }

    if (blk < 128) {
        int c = blk >> 1, ph = blk & 1;
        S[t] = g_seg[(c << 8) + t];           // S[j*16+k] = Seg6[c][j][k]
        __syncthreads();
        int k = t & 15, a8l = t >> 4;
#pragma unroll 1
        for (int p = ph * 8; p < ph * 8 + 8; p++) {
            int a8 = (p << 4) | a8l;
            const float2* w = g_lv8 + (a8 << 4);
            float xr0 = 0.f, xi0 = 0.f, xr1 = 0.f, xi1 = 0.f;
#pragma unroll
            for (int j = 0; j < 16; j += 2) {
                float2 o0 = __ldg(&w[j]),     b0 = S[(j << 4) + k];
                float2 o1 = __ldg(&w[j + 1]), b1 = S[((j + 1) << 4) + k];
                cfma(xr0, xi0, o0.x, o0.y, b0.x, b0.y);
                cfma(xr1, xi1, o1.x, o1.y, b1.x, b1.y);
            }
            g_lvec[(((a8 << 6) | c) << 4) + k] = make_float2(xr0 + xr1, xi0 + xi1);
        }
    } else {
        int b2 = blk - 128;
        int c = b2 >> 1, ph = b2 & 1;
        {
            int i = t >> 4, j = t & 15;
            S[(j << 4) | i] = g_seg[(c << 8) + t];  // transposed stage
        }
        __syncthreads();
        int il = t & 15, b8l = t >> 4;
#pragma unroll 1
        for (int p = ph * 8; p < ph * 8 + 8; p++) {
            int b8 = (p << 4) | b8l;
            const float2* w = g_rv8 + (b8 << 4);
            float xr0 = 0.f, xi0 = 0.f, xr1 = 0.f, xi1 = 0.f;
#pragma unroll
            for (int j = 0; j < 16; j += 2) {
                float2 w0 = __ldg(&w[j]),     b0 = S[(j << 4) + il];
                float2 w1 = __ldg(&w[j + 1]), b1 = S[((j + 1) << 4) + il];
                cfma(xr0, xi0, b0.x, b0.y, w0.x, w0.y);
                cfma(xr1, xi1, b1.x, b1.y, w1.x, w1.y);
            }
            g_rvec[(((c << 8) | b8) << 4) + il] = make_float2(xr0 + xr1, xi0 + xi1);
        }
    }
}

// ---------------------------------------------------------------------------
// Main kernel. Walks the binned slot space in 32-aligned warp chunks; a
// warp's 32 slots sit inside one bin (CHUNK and SLOTCAP are multiples of
// 32) -> stage-1 segment idx warp-uniform -> rotated LDS.128 dedups to
// broadcast. Dead slots skip warp-uniformly. Block 0 also processes the
// overflow region (unsorted, rare). Output scattered to original indices.
// ---------------------------------------------------------------------------
__global__ __launch_bounds__(512) void k_main(float* __restrict__ out, int N) {
    extern __shared__ float2 smem_all[];
    float2* sSeg = smem_all;                    // 16384 float2 = 128 KB

    {
        const float4* src = reinterpret_cast<const float4*>(g_seg);
        float4* dst = reinterpret_cast<float4*>(sSeg);
        for (int e = threadIdx.x; e < 64 * 128; e += blockDim.x) dst[e] = src[e];
    }
    __syncthreads();

    unsigned sb;
    asm("{ .reg .u64 t; cvta.to.shared.u64 t, %1; cvt.u32.u64 %0, t; }"
        : "=r"(sb) : "l"(smem_all));
    const unsigned stgb   = sb + 131072u;
    const unsigned lane   = threadIdx.x & 31u;
    const unsigned rot    = threadIdx.x & 7u;
    const unsigned rot16  = rot << 4;
    const unsigned rot256 = rot << 8;
    const unsigned myStg  = stgb + ((unsigned)threadIdx.x << 7);
    const unsigned warpStg = stgb + ((unsigned)(threadIdx.x & ~31u) << 7);
    const int sub    = (int)(lane >> 3);
    const int chunku = (int)(lane & 7);

    int start = blockIdx.x * CHUNK;
    int end = min(start + CHUNK, MAIN_SLOTS);

    for (int pass = 0; pass < 2; pass++) {
        if (pass == 1) {
            if (blockIdx.x != 0) break;                 // overflow: block 0 only
            start = OV_BASE;
            end = OV_BASE + __ldg(&g_binCount[NBIN]);
            if (end == start) break;
        }

        for (int base = start + (int)((threadIdx.x >> 5) << 5); base < end;
             base += (int)blockDim.x) {
            int cnt_lim;
            if (pass == 0) {
                unsigned bin = (unsigned)base / SLOTCAP;
                int local = base - (int)bin * SLOTCAP;
                int cnt = __ldg(&g_binCount[bin]);
                if (local >= cnt) continue;             // warp-uniform skip
                cnt_lim = cnt - local;                  // actives in this warp
            } else {
                cnt_lim = end - base;
            }
            bool active = (int)lane < cnt_lim;

            ulonglong2 rec = active ? __ldg(&g_xs[base + (int)lane])
                                    : make_ulonglong2(0ull, 0ull);
            ull packed = rec.x;
            int orig = (int)(unsigned)rec.y;
            unsigned idxl = (unsigned)(packed >> 50);
            unsigned idxr = (unsigned)packed & 0x3FFFu;
            ull sp = packed << 14;

            // ---- staged Lvec gather (slots swizzled by owner&7) ----
#pragma unroll
            for (int g = 0; g < 8; g++) {
                int owner = (g << 2) + sub;
                unsigned oidx = __shfl_sync(0xFFFFFFFFu, idxl, owner);
                const char* p = (const char*)g_lvec + ((size_t)oidx << 7) + (chunku << 4);
                ull a, b; ldg128(p, a, b);
                unsigned slot = (unsigned)(chunku ^ (owner & 7));
                sts128(warpStg + ((unsigned)owner << 7) + (slot << 4), a, b);
            }
            __syncwarp();

            float mr[16], mi[16];
#pragma unroll
            for (int u = 0; u < 8; u++) {
                unsigned slot = (unsigned)u ^ rot;
                ull a, b; lds128(myStg + (slot << 4), a, b);
                unpack2(a, mr[2 * u],     mi[2 * u]);
                unpack2(b, mr[2 * u + 1], mi[2 * u + 1]);
            }
            __syncwarp();

            // ---- matvec 1 (stage-1 idx warp-uniform in pass 0) ----
            {
                unsigned idx = (unsigned)(sp >> 58);
                sp <<= 6;
                unsigned mb = sb + (idx << 11);
                ull P[16], Q[16];
#pragma unroll
                for (int e = 0; e < 16; e++) { P[e] = 0ull; Q[e] = 0ull; }
                unsigned pu[8];
#pragma unroll
                for (int u = 0; u < 8; u++) pu[u] = mb + ((rot16 + (u << 4)) & 127u);
#pragma unroll
                for (int i = 0; i < 16; i++) {
                    float ar = mr[i], ai = mi[i];
                    ull arr = pack2(ar, ar), ai2 = pack2(ai, -ai);
#pragma unroll
                    for (int u = 0; u < 8; u++) {
                        ull b0, b1;
                        lds128(pu[u] + (unsigned)(i << 7), b0, b1);
                        P[2 * u]     = ffma2(arr, b0, P[2 * u]);
                        Q[2 * u]     = ffma2(ai2, b0, Q[2 * u]);
                        P[2 * u + 1] = ffma2(arr, b1, P[2 * u + 1]);
                        Q[2 * u + 1] = ffma2(ai2, b1, Q[2 * u + 1]);
                    }
                }
#pragma unroll
                for (int e = 0; e < 16; e++) {
                    float pl, ph, ql, qh;
                    unpack2(P[e], pl, ph);
                    unpack2(Q[e], ql, qh);
                    mr[e] = pl + qh;
                    mi[e] = ph + ql;
                }
            }

            // ---- matvecs 2..6 ----
#pragma unroll 1
            for (int kseg = 1; kseg < 6; kseg++) {
                unsigned idx = (unsigned)(sp >> 58);
                sp <<= 6;
                unsigned mb = sb + (idx << 11);
                ull P[16], Q[16];
#pragma unroll
                for (int e = 0; e < 16; e++) { P[e] = 0ull; Q[e] = 0ull; }
                unsigned pu[8];
#pragma unroll
                for (int u = 0; u < 8; u++) pu[u] = mb + ((rot16 + (u << 4)) & 127u);
#pragma unroll
                for (int spn = 0; spn < 8; spn++) {
                    unsigned row = (rot256 + (unsigned)(spn << 8)) & 2047u;
#pragma unroll
                    for (int hf = 0; hf < 2; hf++) {
                        float ar = mr[2 * spn + hf], ai = mi[2 * spn + hf];
                        ull arr = pack2(ar, ar), ai2 = pack2(ai, -ai);
#pragma unroll
                        for (int u = 0; u < 8; u++) {
                            ull b0, b1;
                            lds128(pu[u] + row + (unsigned)(hf << 7), b0, b1);
                            P[2 * u]     = ffma2(arr, b0, P[2 * u]);
                            Q[2 * u]     = ffma2(ai2, b0, Q[2 * u]);
                            P[2 * u + 1] = ffma2(arr, b1, P[2 * u + 1]);
                            Q[2 * u + 1] = ffma2(ai2, b1, Q[2 * u + 1]);
                        }
                    }
                }
#pragma unroll
                for (int e = 0; e < 16; e++) {
                    float pl, ph, ql, qh;
                    unpack2(P[e], pl, ph);
                    unpack2(Q[e], ql, qh);
                    mr[e] = pl + qh;
                    mi[e] = ph + ql;
                }
            }

            // ---- staged Rvec gather ----
#pragma unroll
            for (int g = 0; g < 8; g++) {
                int owner = (g << 2) + sub;
                unsigned oidx = __shfl_sync(0xFFFFFFFFu, idxr, owner);
                const char* p = (const char*)g_rvec + ((size_t)oidx << 7) + (chunku << 4);
                ull a, b; ldg128(p, a, b);
                sts128(warpStg + ((unsigned)owner << 7) + ((unsigned)chunku << 4), a, b);
            }
            __syncwarp();

            float accr = 0.f, acci = 0.f;
#pragma unroll
            for (int u = 0; u < 8; u++) {
                unsigned lp = (u + rot) & 7u;
                ull a, b; lds128(myStg + (lp << 4), a, b);
                float c0x, c0y, c1x, c1y;
                unpack2(a, c0x, c0y);
                unpack2(b, c1x, c1y);
                int e0 = 2 * u, e1 = 2 * u + 1;
                accr = fmaf(mr[e0], c0x, accr);  accr = fmaf(-mi[e0], c0y, accr);
                acci = fmaf(mr[e0], c0y, acci);  acci = fmaf(mi[e0], c0x, acci);
                accr = fmaf(mr[e1], c1x, accr);  accr = fmaf(-mi[e1], c1y, accr);
                acci = fmaf(mr[e1], c1y, acci);  acci = fmaf(mi[e1], c1x, acci);
            }
            __syncwarp();

            if (active) {
                out[orig]     = accr;
                out[N + orig] = acci;
            }
        }
    }
}

// ---------------------------------------------------------------------------
// kernel_launch
// inputs (metadata order): x, left_r, left_i, bulk_r, bulk_i, right_r, right_i
// out: float32, [2, N] flattened (re then im)
// Order [nop, k1, k2, k_main] so ncu -s 5 (2 harness pre-launches) profiles
// k_main.
// ---------------------------------------------------------------------------
extern "C" void kernel_launch(void* const* d_in, const int* in_sizes, int n_in,
                              void* d_out, int out_size) {
    const int*   x       = (const int*)d_in[0];
    const float* left_r  = (const float*)d_in[1];
    const float* left_i  = (const float*)d_in[2];
    const float* bulk_r  = (const float*)d_in[3];
    const float* bulk_i  = (const float*)d_in[4];
    const float* right_r = (const float*)d_in[5];
    const float* right_i = (const float*)d_in[6];
    float* out = (float*)d_out;

    int N = in_sizes[0] / 64;

    static const size_t kSmem = 192 * 1024;  // 128 KB table + 64 KB staging
    cudaFuncSetAttribute(k_main, cudaFuncAttributeMaxDynamicSharedMemorySize,
                         (int)kSmem);

    k_nop<<<1, 32>>>();
    k1<<<320, 512>>>(x, N, bulk_r, bulk_i, left_r, left_i, right_r, right_i);
    k2<<<256, 256>>>();
    k_main<<<148, 512, kSmem>>>(out, N);
}

// round 13
// speedup vs baseline: 1.3727x; 1.3727x over previous
#include <cuda_runtime.h>
#include <cstdint>

// ---------------------------------------------------------------------------
// MPS amplitude contraction, segment-table approach (v13).
// amplitude(s) = left[x0] . B[x1] ... B[x62] . right[x63]   (complex, D=16)
//
// Split: Lvec covers x0..x13 (14 bits), 6 x Seg6 cover x14..x49 (36 bits),
//        Rvec covers x50..x63 (14 bits).
// v13 = R9 core (no sorting/binning) + 640 threads (20 warps) enabled by
//       split accumulators (P/Q 8 regs, two u-half passes per matvec).
// Pipeline: k0(pack) -> kA(Seg6 build) -> kB(table expansion) -> k_main.
// ---------------------------------------------------------------------------

typedef unsigned long long ull;

__device__ float2 g_seg [64 * 256];
__device__ float2 g_lv8 [256 * 16];
__device__ float2 g_rv8 [256 * 16];
__device__ float2 g_lvec[16384 * 16];
__device__ float2 g_rvec[16384 * 16];
__device__ ull    g_xpack[131072];

// ---- packed fp32x2 helpers ----
__device__ __forceinline__ ull pack2(float lo, float hi) {
    ull r; asm("mov.b64 %0, {%1,%2};" : "=l"(r) : "f"(lo), "f"(hi)); return r;
}
__device__ __forceinline__ void unpack2(ull v, float& lo, float& hi) {
    asm("mov.b64 {%0,%1}, %2;" : "=f"(lo), "=f"(hi) : "l"(v));
}
__device__ __forceinline__ ull ffma2(ull a, ull b, ull c) {
    ull d; asm("fma.rn.f32x2 %0, %1, %2, %3;" : "=l"(d) : "l"(a), "l"(b), "l"(c));
    return d;
}
__device__ __forceinline__ void lds128(unsigned addr, ull& p0, ull& p1) {
    asm volatile("ld.shared.v2.b64 {%0,%1}, [%2];" : "=l"(p0), "=l"(p1) : "r"(addr));
}
__device__ __forceinline__ void sts128(unsigned addr, ull p0, ull p1) {
    asm volatile("st.shared.v2.b64 [%0], {%1,%2};" :: "r"(addr), "l"(p0), "l"(p1));
}
__device__ __forceinline__ void ldg128(const void* p, ull& p0, ull& p1) {
    asm volatile("ld.global.nc.v2.b64 {%0,%1}, [%2];" : "=l"(p0), "=l"(p1) : "l"(p));
}

// scalar complex fma: (rr,ri) += (ax+i ay) * (bx+i by)
__device__ __forceinline__ void cfma(float& rr, float& ri, float ax, float ay,
                                     float bx, float by) {
    rr = fmaf(ax, bx, rr);
    rr = fmaf(-ay, by, rr);
    ri = fmaf(ax, by, ri);
    ri = fmaf(ay, bx, ri);
}

// 16x16 complex matmul, one output element per thread (e = i*16+k, 256 thr)
__device__ __forceinline__ void mm16(const float2* A, const float2* Bm,
                                     float2* C, int e) {
    int i = e >> 4, k = e & 15;
    float xr0 = 0.f, xi0 = 0.f, xr1 = 0.f, xi1 = 0.f;
#pragma unroll
    for (int j = 0; j < 16; j += 2) {
        float2 a0 = A[(i << 4) + j],     b0 = Bm[(j << 4) + k];
        float2 a1 = A[(i << 4) + j + 1], b1 = Bm[((j + 1) << 4) + k];
        cfma(xr0, xi0, a0.x, a0.y, b0.x, b0.y);
        cfma(xr1, xi1, a1.x, a1.y, b1.x, b1.y);
    }
    C[e] = make_float2(xr0 + xr1, xi0 + xi1);
}

// ---------------------------------------------------------------------------
// k0_pack: warp W packs samples [32W, 32W+32); packed bit (63-t) = x_t.
// ---------------------------------------------------------------------------
__global__ void k0_pack(const int* __restrict__ x, int N) {
    int W = (blockIdx.x * blockDim.x + threadIdx.x) >> 5;
    int lane = threadIdx.x & 31;
    int s0 = W << 5;
    if (s0 >= N) return;
    ull mine = 0;
#pragma unroll 4
    for (int q = 0; q < 32; q++) {
        size_t base = (size_t)(s0 + q) << 6;
        unsigned b0 = __ballot_sync(0xFFFFFFFFu, x[base + lane] & 1);
        unsigned b1 = __ballot_sync(0xFFFFFFFFu, x[base + 32 + lane] & 1);
        ull packed = ((ull)__brev(b0) << 32) | (ull)__brev(b1);
        if (lane == q) mine = packed;
    }
    g_xpack[s0 + lane] = mine;
}

// ---------------------------------------------------------------------------
// kA: 64 blocks x 512 threads. Block c builds Seg6[c]; the two Seg3 trees
// (a = c>>3, b = c&7) run in parallel on thread-halves (3 matmul rounds).
// Also emits Lv2/Rv2 -> Lv8/Rv8 slices.
// ---------------------------------------------------------------------------
__global__ __launch_bounds__(512) void kA(
        const float* __restrict__ br_, const float* __restrict__ bi_,
        const float* __restrict__ lr_, const float* __restrict__ li_,
        const float* __restrict__ rr_, const float* __restrict__ ri_) {
    __shared__ float2 sB[512], sT[2][256], sP[2][256], sS6[256];
    __shared__ float2 sLv2[64], sRv2[64];
    __shared__ float sLr[32], sLi[32], sRr[32], sRi[32];
    int e = threadIdx.x, c = blockIdx.x;
    int half = e >> 8, e2 = e & 255;

    sB[e] = make_float2(br_[e], bi_[e]);
    if (e < 32) { sLr[e] = lr_[e]; sLi[e] = li_[e]; sRr[e] = rr_[e]; sRi[e] = ri_[e]; }
    __syncthreads();

    int a = c >> 3, b = c & 7;
    int v = half ? b : a;
    mm16(sB + (((v >> 1) & 1) << 8), sB + ((v & 1) << 8), sT[half], e2);
    __syncthreads();
    mm16(sB + ((v >> 2) << 8), sT[half], sP[half], e2);
    __syncthreads();
    if (half == 0) mm16(sP[0], sP[1], sS6, e2);     // Seg6[c] = Seg3[a].Seg3[b]
    __syncthreads();

    if (half == 0) g_seg[(c << 8) + e2] = sS6[e2];

    if (e < 64) {  // Lv2[(s<<1)|bb][k] = sum_j left[s][j] * B[bb][j][k]
        int vv = e >> 4, k = e & 15, s = vv >> 1, bb = vv & 1;
        float xr = 0.f, xi = 0.f;
#pragma unroll
        for (int j = 0; j < 16; j++) {
            float2 m = sB[(bb << 8) + (j << 4) + k];
            cfma(xr, xi, sLr[s * 16 + j], sLi[s * 16 + j], m.x, m.y);
        }
        sLv2[e] = make_float2(xr, xi);
    } else if (e < 128) {  // Rv2[(bb<<1)|r][i] = sum_j B[bb][i][j] * right[r][j]
        int t2 = e - 64, vv = t2 >> 4, i = t2 & 15, bb = vv >> 1, r = vv & 1;
        float xr = 0.f, xi = 0.f;
#pragma unroll
        for (int j = 0; j < 16; j++) {
            float2 m = sB[(bb << 8) + (i << 4) + j];
            cfma(xr, xi, m.x, m.y, sRr[r * 16 + j], sRi[r * 16 + j]);
        }
        sRv2[t2] = make_float2(xr, xi);
    }
    __syncthreads();

    if (e < 64) {  // Lv8[(a2<<6)|c][k] = sum_j Lv2[a2][j] * Seg6[c][j][k]
        int a2 = e >> 4, k = e & 15;
        float xr = 0.f, xi = 0.f;
#pragma unroll
        for (int j = 0; j < 16; j++) {
            float2 o = sLv2[(a2 << 4) + j];
            float2 m = sS6[(j << 4) + k];
            cfma(xr, xi, o.x, o.y, m.x, m.y);
        }
        g_lv8[(((a2 << 6) | c) << 4) + k] = make_float2(xr, xi);
    } else if (e < 128) {  // Rv8[(c<<2)|b2][i] = sum_j Seg6[c][i][j] * Rv2[b2][j]
        int t2 = e - 64, b2 = t2 >> 4, i = t2 & 15;
        float xr = 0.f, xi = 0.f;
#pragma unroll
        for (int j = 0; j < 16; j++) {
            float2 m = sS6[(i << 4) + j];
            float2 w = sRv2[(b2 << 4) + j];
            cfma(xr, xi, m.x, m.y, w.x, w.y);
        }
        g_rv8[(((c << 2) | b2) << 4) + i] = make_float2(xr, xi);
    }
}

// ---------------------------------------------------------------------------
// kB: 256 blocks x 256 threads. Table expansion with dual-acc ILP, p-split.
// Blocks 0..127:  L side, c = blk>>1, p-half = blk&1.
// Blocks 128..255: R side, c = (blk-128)>>1, p-half = (blk-128)&1.
// ---------------------------------------------------------------------------
__global__ void kB() {
    __shared__ float2 S[256];
    int blk = blockIdx.x;
    int t = threadIdx.x;

    if (blk < 128) {
        int c = blk >> 1, ph = blk & 1;
        S[t] = g_seg[(c << 8) + t];           // S[j*16+k] = Seg6[c][j][k]
        __syncthreads();
        int k = t & 15, a8l = t >> 4;
#pragma unroll 1
        for (int p = ph * 8; p < ph * 8 + 8; p++) {
            int a8 = (p << 4) | a8l;
            const float2* w = g_lv8 + (a8 << 4);
            float xr0 = 0.f, xi0 = 0.f, xr1 = 0.f, xi1 = 0.f;
#pragma unroll
            for (int j = 0; j < 16; j += 2) {
                float2 o0 = __ldg(&w[j]),     b0 = S[(j << 4) + k];
                float2 o1 = __ldg(&w[j + 1]), b1 = S[((j + 1) << 4) + k];
                cfma(xr0, xi0, o0.x, o0.y, b0.x, b0.y);
                cfma(xr1, xi1, o1.x, o1.y, b1.x, b1.y);
            }
            g_lvec[(((a8 << 6) | c) << 4) + k] = make_float2(xr0 + xr1, xi0 + xi1);
        }
    } else {
        int b2 = blk - 128;
        int c = b2 >> 1, ph = b2 & 1;
        {
            int i = t >> 4, j = t & 15;
            S[(j << 4) | i] = g_seg[(c << 8) + t];  // transposed stage
        }
        __syncthreads();
        int il = t & 15, b8l = t >> 4;
#pragma unroll 1
        for (int p = ph * 8; p < ph * 8 + 8; p++) {
            int b8 = (p << 4) | b8l;
            const float2* w = g_rv8 + (b8 << 4);
            float xr0 = 0.f, xi0 = 0.f, xr1 = 0.f, xi1 = 0.f;
#pragma unroll
            for (int j = 0; j < 16; j += 2) {
                float2 w0 = __ldg(&w[j]),     b0 = S[(j << 4) + il];
                float2 w1 = __ldg(&w[j + 1]), b1 = S[((j + 1) << 4) + il];
                cfma(xr0, xi0, b0.x, b0.y, w0.x, w0.y);
                cfma(xr1, xi1, b1.x, b1.y, w1.x, w1.y);
            }
            g_rvec[(((c << 8) | b8) << 4) + il] = make_float2(xr0 + xr1, xi0 + xi1);
        }
    }
}

// ---------------------------------------------------------------------------
// Main kernel. 640 threads (20 warps) per block; split accumulators (two
// u-half passes per matvec, P/Q of 8) keep regs <= ~102. One thread per
// sample, balanced contiguous chunk per block, warp-uniform outer loop.
// Smem: 128 KB Seg6 table + 80 KB gather staging. Lvec/Rvec fetched
// warp-cooperatively and staged; table column pairs read in lane-rotated
// order (deterministic 4-phase LDS.128). Register pair u of the state holds
// logical pair (u+rot)&7 after the first matvec.
// ---------------------------------------------------------------------------
__global__ __launch_bounds__(640, 1) void k_main(float* __restrict__ out, int N) {
    extern __shared__ float2 smem_all[];
    float2* sSeg = smem_all;                    // 16384 float2 = 128 KB

    {
        const float4* src = reinterpret_cast<const float4*>(g_seg);
        float4* dst = reinterpret_cast<float4*>(sSeg);
        for (int e = threadIdx.x; e < 64 * 128; e += blockDim.x) dst[e] = src[e];
    }
    __syncthreads();

    unsigned sb;
    asm("{ .reg .u64 t; cvta.to.shared.u64 t, %1; cvt.u32.u64 %0, t; }"
        : "=r"(sb) : "l"(smem_all));
    const unsigned stgb   = sb + 131072u;            // staging base (bytes)
    const unsigned lane   = threadIdx.x & 31u;
    const unsigned rot    = threadIdx.x & 7u;
    const unsigned rot16  = rot << 4;
    const unsigned rot256 = rot << 8;
    const unsigned myStg  = stgb + ((unsigned)threadIdx.x << 7);
    const unsigned warpStg = stgb + ((unsigned)(threadIdx.x & ~31u) << 7);
    const int sub    = (int)(lane >> 3);             // 0..3
    const int chunku = (int)(lane & 7);              // 16B chunk this lane moves

    int chunk = (N + gridDim.x - 1) / gridDim.x;
    int start = blockIdx.x * chunk;
    int end = min(start + chunk, N);

    for (int base = start + (int)((threadIdx.x >> 5) << 5); base < end;
         base += (int)blockDim.x) {
        int s = base + (int)lane;
        bool active = s < end;
        ull packed = active ? __ldg(&g_xpack[s]) : 0ull;
        unsigned idxl = (unsigned)(packed >> 50);         // x0..x13
        unsigned idxr = (unsigned)packed & 0x3FFFu;       // x50..x63
        ull sp = packed << 14;                            // x14 at bit 63

        // ---- staged Lvec gather (slots swizzled by owner&7) ----
#pragma unroll
        for (int g = 0; g < 8; g++) {
            int owner = (g << 2) + sub;
            unsigned oidx = __shfl_sync(0xFFFFFFFFu, idxl, owner);
            const char* p = (const char*)g_lvec + ((size_t)oidx << 7) + (chunku << 4);
            ull a, b; ldg128(p, a, b);
            unsigned slot = (unsigned)(chunku ^ (owner & 7));
            sts128(warpStg + ((unsigned)owner << 7) + (slot << 4), a, b);
        }
        __syncwarp();

        float mr[16], mi[16];
#pragma unroll
        for (int u = 0; u < 8; u++) {                    // logical order
            unsigned slot = (unsigned)u ^ rot;
            ull a, b; lds128(myStg + (slot << 4), a, b);
            unpack2(a, mr[2 * u],     mi[2 * u]);
            unpack2(b, mr[2 * u + 1], mi[2 * u + 1]);
        }
        __syncwarp();   // all reads done before staging is reused below

        // ---- matvec 1: m in logical order, rows by immediate offsets.
        //      Two u-half passes with P/Q of 8 (register diet). ----
        {
            unsigned idx = (unsigned)(sp >> 58);
            sp <<= 6;
            unsigned mb = sb + (idx << 11);
            float nr[16], ni[16];
#pragma unroll
            for (int h = 0; h < 2; h++) {
                ull P[8], Q[8];
#pragma unroll
                for (int e = 0; e < 8; e++) { P[e] = 0ull; Q[e] = 0ull; }
                unsigned pu[4];
#pragma unroll
                for (int v = 0; v < 4; v++)
                    pu[v] = mb + ((rot16 + ((unsigned)(h * 4 + v) << 4)) & 127u);
#pragma unroll
                for (int i = 0; i < 16; i++) {
                    float ar = mr[i], ai = mi[i];
                    ull arr = pack2(ar, ar), ai2 = pack2(ai, -ai);
#pragma unroll
                    for (int v = 0; v < 4; v++) {
                        ull b0, b1;
                        lds128(pu[v] + (unsigned)(i << 7), b0, b1);
                        P[2 * v]     = ffma2(arr, b0, P[2 * v]);
                        Q[2 * v]     = ffma2(ai2, b0, Q[2 * v]);
                        P[2 * v + 1] = ffma2(arr, b1, P[2 * v + 1]);
                        Q[2 * v + 1] = ffma2(ai2, b1, Q[2 * v + 1]);
                    }
                }
#pragma unroll
                for (int e = 0; e < 8; e++) {
                    float pl, ph, ql, qh;
                    unpack2(P[e], pl, ph);
                    unpack2(Q[e], ql, qh);
                    nr[h * 8 + e] = pl + qh;   // nr = ar*bx - ai*by
                    ni[h * 8 + e] = ph + ql;   // ni = ar*by + ai*bx
                }
            }
#pragma unroll
            for (int e = 0; e < 16; e++) { mr[e] = nr[e]; mi[e] = ni[e]; }
        }

        // ---- matvecs 2..6: state pair u holds logical pair (u+rot)&7 ----
#pragma unroll 1
        for (int kseg = 1; kseg < 6; kseg++) {
            unsigned idx = (unsigned)(sp >> 58);
            sp <<= 6;
            unsigned mb = sb + (idx << 11);
            float nr[16], ni[16];
#pragma unroll
            for (int h = 0; h < 2; h++) {
                ull P[8], Q[8];
#pragma unroll
                for (int e = 0; e < 8; e++) { P[e] = 0ull; Q[e] = 0ull; }
                unsigned pu[4];
#pragma unroll
                for (int v = 0; v < 4; v++)
                    pu[v] = mb + ((rot16 + ((unsigned)(h * 4 + v) << 4)) & 127u);
#pragma unroll
                for (int spn = 0; spn < 8; spn++) {
                    unsigned row = (rot256 + (unsigned)(spn << 8)) & 2047u;
#pragma unroll
                    for (int hf = 0; hf < 2; hf++) {
                        float ar = mr[2 * spn + hf], ai = mi[2 * spn + hf];
                        ull arr = pack2(ar, ar), ai2 = pack2(ai, -ai);
#pragma unroll
                        for (int v = 0; v < 4; v++) {
                            ull b0, b1;
                            lds128(pu[v] + row + (unsigned)(hf << 7), b0, b1);
                            P[2 * v]     = ffma2(arr, b0, P[2 * v]);
                            Q[2 * v]     = ffma2(ai2, b0, Q[2 * v]);
                            P[2 * v + 1] = ffma2(arr, b1, P[2 * v + 1]);
                            Q[2 * v + 1] = ffma2(ai2, b1, Q[2 * v + 1]);
                        }
                    }
                }
#pragma unroll
                for (int e = 0; e < 8; e++) {
                    float pl, ph, ql, qh;
                    unpack2(P[e], pl, ph);
                    unpack2(Q[e], ql, qh);
                    nr[h * 8 + e] = pl + qh;
                    ni[h * 8 + e] = ph + ql;
                }
            }
#pragma unroll
            for (int e = 0; e < 16; e++) { mr[e] = nr[e]; mi[e] = ni[e]; }
        }

        // ---- staged Rvec gather (unswizzled slots; read order is rotated) ----
#pragma unroll
        for (int g = 0; g < 8; g++) {
            int owner = (g << 2) + sub;
            unsigned oidx = __shfl_sync(0xFFFFFFFFu, idxr, owner);
            const char* p = (const char*)g_rvec + ((size_t)oidx << 7) + (chunku << 4);
            ull a, b; ldg128(p, a, b);
            sts128(warpStg + ((unsigned)owner << 7) + ((unsigned)chunku << 4), a, b);
        }
        __syncwarp();

        float accr = 0.f, acci = 0.f;
#pragma unroll
        for (int u = 0; u < 8; u++) {
            unsigned lp = (u + rot) & 7u;               // logical pair at step u
            ull a, b; lds128(myStg + (lp << 4), a, b);
            float c0x, c0y, c1x, c1y;
            unpack2(a, c0x, c0y);
            unpack2(b, c1x, c1y);
            int e0 = 2 * u, e1 = 2 * u + 1;
            accr = fmaf(mr[e0], c0x, accr);  accr = fmaf(-mi[e0], c0y, accr);
            acci = fmaf(mr[e0], c0y, acci);  acci = fmaf(mi[e0], c0x, acci);
            accr = fmaf(mr[e1], c1x, accr);  accr = fmaf(-mi[e1], c1y, accr);
            acci = fmaf(mr[e1], c1y, acci);  acci = fmaf(mi[e1], c1x, acci);
        }
        __syncwarp();   // staging reused next iteration

        if (active) {
            out[s]     = accr;
            out[N + s] = acci;
        }
    }
}

// ---------------------------------------------------------------------------
// kernel_launch
// inputs (metadata order): x, left_r, left_i, bulk_r, bulk_i, right_r, right_i
// out: float32, [2, N] flattened (re then im)
// Order [k0, kA, kB, k_main]: ncu -s 5 (2 harness pre-launches) profiles
// k_main at index 3.
// ---------------------------------------------------------------------------
extern "C" void kernel_launch(void* const* d_in, const int* in_sizes, int n_in,
                              void* d_out, int out_size) {
    const int*   x       = (const int*)d_in[0];
    const float* left_r  = (const float*)d_in[1];
    const float* left_i  = (const float*)d_in[2];
    const float* bulk_r  = (const float*)d_in[3];
    const float* bulk_i  = (const float*)d_in[4];
    const float* right_r = (const float*)d_in[5];
    const float* right_i = (const float*)d_in[6];
    float* out = (float*)d_out;

    int N = in_sizes[0] / 64;

    static const size_t kSmem = 131072 + 640 * 128;  // 128 KB table + 80 KB staging
    cudaFuncSetAttribute(k_main, cudaFuncAttributeMaxDynamicSharedMemorySize,
                         (int)kSmem);

    k0_pack<<<(131072 + 255) / 256, 256>>>(x, N);
    kA<<<64, 512>>>(bulk_r, bulk_i, left_r, left_i, right_r, right_i);
    kB<<<256, 256>>>();
    k_main<<<148, 640, kSmem>>>(out, N);
}

// round 15
// speedup vs baseline: 1.5148x; 1.1036x over previous
#include <cuda_runtime.h>
#include <cstdint>

// ---------------------------------------------------------------------------
// MPS amplitude contraction, segment-table approach (v14, resubmitted —
// R14 was an infra failure; source unchanged for clean attribution).
// amplitude(s) = left[x0] . B[x1] ... B[x62] . right[x63]   (complex, D=16)
//
// Split: Lvec covers x0..x13 (14 bits), 6 x Seg6 cover x14..x49 (36 bits),
//        Rvec covers x50..x63 (14 bits).
// v14: k_main = R9-proven 512-thread hot loop (63.9 us measured).
//      Pack fused into kA as parallel block range -> 3-launch pipeline:
//      kA'(pack blocks 0..255 || seg blocks 256..319) -> kB(256) -> k_main.
// ---------------------------------------------------------------------------

typedef unsigned long long ull;

__device__ float2 g_seg [64 * 256];
__device__ float2 g_lv8 [256 * 16];
__device__ float2 g_rv8 [256 * 16];
__device__ float2 g_lvec[16384 * 16];
__device__ float2 g_rvec[16384 * 16];
__device__ ull    g_xpack[131072];

// ---- packed fp32x2 helpers ----
__device__ __forceinline__ ull pack2(float lo, float hi) {
    ull r; asm("mov.b64 %0, {%1,%2};" : "=l"(r) : "f"(lo), "f"(hi)); return r;
}
__device__ __forceinline__ void unpack2(ull v, float& lo, float& hi) {
    asm("mov.b64 {%0,%1}, %2;" : "=f"(lo), "=f"(hi) : "l"(v));
}
__device__ __forceinline__ ull ffma2(ull a, ull b, ull c) {
    ull d; asm("fma.rn.f32x2 %0, %1, %2, %3;" : "=l"(d) : "l"(a), "l"(b), "l"(c));
    return d;
}
__device__ __forceinline__ void lds128(unsigned addr, ull& p0, ull& p1) {
    asm volatile("ld.shared.v2.b64 {%0,%1}, [%2];" : "=l"(p0), "=l"(p1) : "r"(addr));
}
__device__ __forceinline__ void sts128(unsigned addr, ull p0, ull p1) {
    asm volatile("st.shared.v2.b64 [%0], {%1,%2};" :: "r"(addr), "l"(p0), "l"(p1));
}
__device__ __forceinline__ void ldg128(const void* p, ull& p0, ull& p1) {
    asm volatile("ld.global.nc.v2.b64 {%0,%1}, [%2];" : "=l"(p0), "=l"(p1) : "l"(p));
}

// scalar complex fma: (rr,ri) += (ax+i ay) * (bx+i by)
__device__ __forceinline__ void cfma(float& rr, float& ri, float ax, float ay,
                                     float bx, float by) {
    rr = fmaf(ax, bx, rr);
    rr = fmaf(-ay, by, rr);
    ri = fmaf(ax, by, ri);
    ri = fmaf(ay, bx, ri);
}

// 16x16 complex matmul, one output element per thread (e = i*16+k, 256 thr)
__device__ __forceinline__ void mm16(const float2* A, const float2* Bm,
                                     float2* C, int e) {
    int i = e >> 4, k = e & 15;
    float xr0 = 0.f, xi0 = 0.f, xr1 = 0.f, xi1 = 0.f;
#pragma unroll
    for (int j = 0; j < 16; j += 2) {
        float2 a0 = A[(i << 4) + j],     b0 = Bm[(j << 4) + k];
        float2 a1 = A[(i << 4) + j + 1], b1 = Bm[((j + 1) << 4) + k];
        cfma(xr0, xi0, a0.x, a0.y, b0.x, b0.y);
        cfma(xr1, xi1, a1.x, a1.y, b1.x, b1.y);
    }
    C[e] = make_float2(xr0 + xr1, xi0 + xi1);
}

// ---------------------------------------------------------------------------
// kA': 320 blocks x 512 threads.
// Blocks 0..255: pack 512 samples each (16 warps x 32 samples, warp-ballot);
//   packed bit (63-t) = x_t. Straight write to g_xpack (no binning).
// Blocks 256..319: block c-256 builds Seg6[c] (parallel Seg3 trees on
//   thread-halves) + Lv2/Rv2 -> Lv8/Rv8 slices.
// ---------------------------------------------------------------------------
__global__ __launch_bounds__(512) void kA(
        const int* __restrict__ x, int N,
        const float* __restrict__ br_, const float* __restrict__ bi_,
        const float* __restrict__ lr_, const float* __restrict__ li_,
        const float* __restrict__ rr_, const float* __restrict__ ri_) {
    if (blockIdx.x < 256) {
        int W = (blockIdx.x << 4) + (threadIdx.x >> 5);
        int lane = threadIdx.x & 31;
        int s0 = W << 5;
        if (s0 >= N) return;
        ull mine = 0;
#pragma unroll 4
        for (int q = 0; q < 32; q++) {
            size_t base = (size_t)(s0 + q) << 6;
            unsigned b0 = __ballot_sync(0xFFFFFFFFu, x[base + lane] & 1);
            unsigned b1 = __ballot_sync(0xFFFFFFFFu, x[base + 32 + lane] & 1);
            ull packed = ((ull)__brev(b0) << 32) | (ull)__brev(b1);
            if (lane == q) mine = packed;
        }
        if (s0 + lane < N) g_xpack[s0 + lane] = mine;
        return;
    }

    // ---- Seg6 builder blocks ----
    __shared__ float2 sB[512], sT[2][256], sP[2][256], sS6[256];
    __shared__ float2 sLv2[64], sRv2[64];
    __shared__ float sLr[32], sLi[32], sRr[32], sRi[32];
    int e = threadIdx.x, c = blockIdx.x - 256;
    int half = e >> 8, e2 = e & 255;

    sB[e] = make_float2(br_[e], bi_[e]);
    if (e < 32) { sLr[e] = lr_[e]; sLi[e] = li_[e]; sRr[e] = rr_[e]; sRi[e] = ri_[e]; }
    __syncthreads();

    int a = c >> 3, b = c & 7;
    int v = half ? b : a;
    mm16(sB + (((v >> 1) & 1) << 8), sB + ((v & 1) << 8), sT[half], e2);
    __syncthreads();
    mm16(sB + ((v >> 2) << 8), sT[half], sP[half], e2);
    __syncthreads();
    if (half == 0) mm16(sP[0], sP[1], sS6, e2);     // Seg6[c] = Seg3[a].Seg3[b]
    __syncthreads();

    if (half == 0) g_seg[(c << 8) + e2] = sS6[e2];

    if (e < 64) {  // Lv2[(s<<1)|bb][k] = sum_j left[s][j] * B[bb][j][k]
        int vv = e >> 4, k = e & 15, s = vv >> 1, bb = vv & 1;
        float xr = 0.f, xi = 0.f;
#pragma unroll
        for (int j = 0; j < 16; j++) {
            float2 m = sB[(bb << 8) + (j << 4) + k];
            cfma(xr, xi, sLr[s * 16 + j], sLi[s * 16 + j], m.x, m.y);
        }
        sLv2[e] = make_float2(xr, xi);
    } else if (e < 128) {  // Rv2[(bb<<1)|r][i] = sum_j B[bb][i][j] * right[r][j]
        int t2 = e - 64, vv = t2 >> 4, i = t2 & 15, bb = vv >> 1, r = vv & 1;
        float xr = 0.f, xi = 0.f;
#pragma unroll
        for (int j = 0; j < 16; j++) {
            float2 m = sB[(bb << 8) + (i << 4) + j];
            cfma(xr, xi, m.x, m.y, sRr[r * 16 + j], sRi[r * 16 + j]);
        }
        sRv2[t2] = make_float2(xr, xi);
    }
    __syncthreads();

    if (e < 64) {  // Lv8[(a2<<6)|c][k] = sum_j Lv2[a2][j] * Seg6[c][j][k]
        int a2 = e >> 4, k = e & 15;
        float xr = 0.f, xi = 0.f;
#pragma unroll
        for (int j = 0; j < 16; j++) {
            float2 o = sLv2[(a2 << 4) + j];
            float2 m = sS6[(j << 4) + k];
            cfma(xr, xi, o.x, o.y, m.x, m.y);
        }
        g_lv8[(((a2 << 6) | c) << 4) + k] = make_float2(xr, xi);
    } else if (e < 128) {  // Rv8[(c<<2)|b2][i] = sum_j Seg6[c][i][j] * Rv2[b2][j]
        int t2 = e - 64, b2 = t2 >> 4, i = t2 & 15;
        float xr = 0.f, xi = 0.f;
#pragma unroll
        for (int j = 0; j < 16; j++) {
            float2 m = sS6[(i << 4) + j];
            float2 w = sRv2[(b2 << 4) + j];
            cfma(xr, xi, m.x, m.y, w.x, w.y);
        }
        g_rv8[(((c << 2) | b2) << 4) + i] = make_float2(xr, xi);
    }
}

// ---------------------------------------------------------------------------
// kB: 256 blocks x 256 threads. Table expansion with dual-acc ILP, p-split.
// Blocks 0..127:  L side, c = blk>>1, p-half = blk&1.
// Blocks 128..255: R side, c = (blk-128)>>1, p-half = (blk-128)&1.
// ---------------------------------------------------------------------------
__global__ void kB() {
    __shared__ float2 S[256];
    int blk = blockIdx.x;
    int t = threadIdx.x;

    if (blk < 128) {
        int c = blk >> 1, ph = blk & 1;
        S[t] = g_seg[(c << 8) + t];           // S[j*16+k] = Seg6[c][j][k]
        __syncthreads();
        int k = t & 15, a8l = t >> 4;
#pragma unroll 1
        for (int p = ph * 8; p < ph * 8 + 8; p++) {
            int a8 = (p << 4) | a8l;
            const float2* w = g_lv8 + (a8 << 4);
            float xr0 = 0.f, xi0 = 0.f, xr1 = 0.f, xi1 = 0.f;
#pragma unroll
            for (int j = 0; j < 16; j += 2) {
                float2 o0 = __ldg(&w[j]),     b0 = S[(j << 4) + k];
                float2 o1 = __ldg(&w[j + 1]), b1 = S[((j + 1) << 4) + k];
                cfma(xr0, xi0, o0.x, o0.y, b0.x, b0.y);
                cfma(xr1, xi1, o1.x, o1.y, b1.x, b1.y);
            }
            g_lvec[(((a8 << 6) | c) << 4) + k] = make_float2(xr0 + xr1, xi0 + xi1);
        }
    } else {
        int b2 = blk - 128;
        int c = b2 >> 1, ph = b2 & 1;
        {
            int i = t >> 4, j = t & 15;
            S[(j << 4) | i] = g_seg[(c << 8) + t];  // transposed stage
        }
        __syncthreads();
        int il = t & 15, b8l = t >> 4;
#pragma unroll 1
        for (int p = ph * 8; p < ph * 8 + 8; p++) {
            int b8 = (p << 4) | b8l;
            const float2* w = g_rv8 + (b8 << 4);
            float xr0 = 0.f, xi0 = 0.f, xr1 = 0.f, xi1 = 0.f;
#pragma unroll
            for (int j = 0; j < 16; j += 2) {
                float2 w0 = __ldg(&w[j]),     b0 = S[(j << 4) + il];
                float2 w1 = __ldg(&w[j + 1]), b1 = S[((j + 1) << 4) + il];
                cfma(xr0, xi0, b0.x, b0.y, w0.x, w0.y);
                cfma(xr1, xi1, b1.x, b1.y, w1.x, w1.y);
            }
            g_rvec[(((c << 8) | b8) << 4) + il] = make_float2(xr0 + xr1, xi0 + xi1);
        }
    }
}

// ---------------------------------------------------------------------------
// Main kernel (R9-proven, 63.9 us measured). 512 threads, one per sample,
// balanced contiguous chunk per block, warp-uniform outer loop.
// Smem: 128 KB Seg6 table + 64 KB gather staging. Lvec/Rvec fetched
// warp-cooperatively and staged; table column pairs read in lane-rotated
// order (deterministic 4-phase LDS.128). Register pair u of the state holds
// logical pair (u+rot)&7 after the first matvec.
// ---------------------------------------------------------------------------
__global__ __launch_bounds__(512) void k_main(float* __restrict__ out, int N) {
    extern __shared__ float2 smem_all[];
    float2* sSeg = smem_all;                    // 16384 float2 = 128 KB

    {
        const float4* src = reinterpret_cast<const float4*>(g_seg);
        float4* dst = reinterpret_cast<float4*>(sSeg);
        for (int e = threadIdx.x; e < 64 * 128; e += blockDim.x) dst[e] = src[e];
    }
    __syncthreads();

    unsigned sb;
    asm("{ .reg .u64 t; cvta.to.shared.u64 t, %1; cvt.u32.u64 %0, t; }"
        : "=r"(sb) : "l"(smem_all));
    const unsigned stgb   = sb + 131072u;            // staging base (bytes)
    const unsigned lane   = threadIdx.x & 31u;
    const unsigned rot    = threadIdx.x & 7u;
    const unsigned rot16  = rot << 4;
    const unsigned rot256 = rot << 8;
    const unsigned myStg  = stgb + ((unsigned)threadIdx.x << 7);
    const unsigned warpStg = stgb + ((unsigned)(threadIdx.x & ~31u) << 7);
    const int sub    = (int)(lane >> 3);             // 0..3
    const int chunku = (int)(lane & 7);              // 16B chunk this lane moves

    int chunk = (N + gridDim.x - 1) / gridDim.x;
    int start = blockIdx.x * chunk;
    int end = min(start + chunk, N);

    for (int base = start + (int)((threadIdx.x >> 5) << 5); base < end;
         base += (int)blockDim.x) {
        int s = base + (int)lane;
        bool active = s < end;
        ull packed = active ? __ldg(&g_xpack[s]) : 0ull;
        unsigned idxl = (unsigned)(packed >> 50);         // x0..x13
        unsigned idxr = (unsigned)packed & 0x3FFFu;       // x50..x63
        ull sp = packed << 14;                            // x14 at bit 63

        // ---- staged Lvec gather (slots swizzled by owner&7) ----
#pragma unroll
        for (int g = 0; g < 8; g++) {
            int owner = (g << 2) + sub;
            unsigned oidx = __shfl_sync(0xFFFFFFFFu, idxl, owner);
            const char* p = (const char*)g_lvec + ((size_t)oidx << 7) + (chunku << 4);
            ull a, b; ldg128(p, a, b);
            unsigned slot = (unsigned)(chunku ^ (owner & 7));
            sts128(warpStg + ((unsigned)owner << 7) + (slot << 4), a, b);
        }
        __syncwarp();

        float mr[16], mi[16];
#pragma unroll
        for (int u = 0; u < 8; u++) {                    // logical order
            unsigned slot = (unsigned)u ^ rot;
            ull a, b; lds128(myStg + (slot << 4), a, b);
            unpack2(a, mr[2 * u],     mi[2 * u]);
            unpack2(b, mr[2 * u + 1], mi[2 * u + 1]);
        }
        __syncwarp();   // all reads done before staging is reused below

        // ---- matvec 1: m in logical order, rows by immediate offsets ----
        {
            unsigned idx = (unsigned)(sp >> 58);
            sp <<= 6;
            unsigned mb = sb + (idx << 11);
            ull P[16], Q[16];
#pragma unroll
            for (int e = 0; e < 16; e++) { P[e] = 0ull; Q[e] = 0ull; }
            unsigned pu[8];
#pragma unroll
            for (int u = 0; u < 8; u++) pu[u] = mb + ((rot16 + (u << 4)) & 127u);
#pragma unroll
            for (int i = 0; i < 16; i++) {
                float ar = mr[i], ai = mi[i];
                ull arr = pack2(ar, ar), ai2 = pack2(ai, -ai);
#pragma unroll
                for (int u = 0; u < 8; u++) {
                    ull b0, b1;
                    lds128(pu[u] + (unsigned)(i << 7), b0, b1);
                    P[2 * u]     = ffma2(arr, b0, P[2 * u]);
                    Q[2 * u]     = ffma2(ai2, b0, Q[2 * u]);
                    P[2 * u + 1] = ffma2(arr, b1, P[2 * u + 1]);
                    Q[2 * u + 1] = ffma2(ai2, b1, Q[2 * u + 1]);
                }
            }
#pragma unroll
            for (int e = 0; e < 16; e++) {
                float pl, ph, ql, qh;
                unpack2(P[e], pl, ph);
                unpack2(Q[e], ql, qh);
                mr[e] = pl + qh;   // nr = ar*bx - ai*by
                mi[e] = ph + ql;   // ni = ar*by + ai*bx
            }
        }

        // ---- matvecs 2..6: state pair u holds logical pair (u+rot)&7 ----
#pragma unroll 1
        for (int kseg = 1; kseg < 6; kseg++) {
            unsigned idx = (unsigned)(sp >> 58);
            sp <<= 6;
            unsigned mb = sb + (idx << 11);
            ull P[16], Q[16];
#pragma unroll
            for (int e = 0; e < 16; e++) { P[e] = 0ull; Q[e] = 0ull; }
            unsigned pu[8];
#pragma unroll
            for (int u = 0; u < 8; u++) pu[u] = mb + ((rot16 + (u << 4)) & 127u);
#pragma unroll
            for (int spn = 0; spn < 8; spn++) {
                unsigned row = (rot256 + (unsigned)(spn << 8)) & 2047u;
#pragma unroll
                for (int hf = 0; hf < 2; hf++) {
                    float ar = mr[2 * spn + hf], ai = mi[2 * spn + hf];
                    ull arr = pack2(ar, ar), ai2 = pack2(ai, -ai);
#pragma unroll
                    for (int u = 0; u < 8; u++) {
                        ull b0, b1;
                        lds128(pu[u] + row + (unsigned)(hf << 7), b0, b1);
                        P[2 * u]     = ffma2(arr, b0, P[2 * u]);
                        Q[2 * u]     = ffma2(ai2, b0, Q[2 * u]);
                        P[2 * u + 1] = ffma2(arr, b1, P[2 * u + 1]);
                        Q[2 * u + 1] = ffma2(ai2, b1, Q[2 * u + 1]);
                    }
                }
            }
#pragma unroll
            for (int e = 0; e < 16; e++) {
                float pl, ph, ql, qh;
                unpack2(P[e], pl, ph);
                unpack2(Q[e], ql, qh);
                mr[e] = pl + qh;
                mi[e] = ph + ql;
            }
        }

        // ---- staged Rvec gather (unswizzled slots; read order is rotated) ----
#pragma unroll
        for (int g = 0; g < 8; g++) {
            int owner = (g << 2) + sub;
            unsigned oidx = __shfl_sync(0xFFFFFFFFu, idxr, owner);
            const char* p = (const char*)g_rvec + ((size_t)oidx << 7) + (chunku << 4);
            ull a, b; ldg128(p, a, b);
            sts128(warpStg + ((unsigned)owner << 7) + ((unsigned)chunku << 4), a, b);
        }
        __syncwarp();

        float accr = 0.f, acci = 0.f;
#pragma unroll
        for (int u = 0; u < 8; u++) {
            unsigned lp = (u + rot) & 7u;               // logical pair at step u
            ull a, b; lds128(myStg + (lp << 4), a, b);
            float c0x, c0y, c1x, c1y;
            unpack2(a, c0x, c0y);
            unpack2(b, c1x, c1y);
            int e0 = 2 * u, e1 = 2 * u + 1;
            accr = fmaf(mr[e0], c0x, accr);  accr = fmaf(-mi[e0], c0y, accr);
            acci = fmaf(mr[e0], c0y, acci);  acci = fmaf(mi[e0], c0x, acci);
            accr = fmaf(mr[e1], c1x, accr);  accr = fmaf(-mi[e1], c1y, accr);
            acci = fmaf(mr[e1], c1y, acci);  acci = fmaf(mi[e1], c1x, acci);
        }
        __syncwarp();   // staging reused next iteration

        if (active) {
            out[s]     = accr;
            out[N + s] = acci;
        }
    }
}

// ---------------------------------------------------------------------------
// kernel_launch
// inputs (metadata order): x, left_r, left_i, bulk_r, bulk_i, right_r, right_i
// out: float32, [2, N] flattened (re then im)
// ---------------------------------------------------------------------------
extern "C" void kernel_launch(void* const* d_in, const int* in_sizes, int n_in,
                              void* d_out, int out_size) {
    const int*   x       = (const int*)d_in[0];
    const float* left_r  = (const float*)d_in[1];
    const float* left_i  = (const float*)d_in[2];
    const float* bulk_r  = (const float*)d_in[3];
    const float* bulk_i  = (const float*)d_in[4];
    const float* right_r = (const float*)d_in[5];
    const float* right_i = (const float*)d_in[6];
    float* out = (float*)d_out;

    int N = in_sizes[0] / 64;

    static const size_t kSmem = 192 * 1024;  // 128 KB table + 64 KB staging
    cudaFuncSetAttribute(k_main, cudaFuncAttributeMaxDynamicSharedMemorySize,
                         (int)kSmem);

    kA<<<320, 512>>>(x, N, bulk_r, bulk_i, left_r, left_i, right_r, right_i);
    kB<<<256, 256>>>();
    k_main<<<148, 512, kSmem>>>(out, N);
}

// round 16
// speedup vs baseline: 1.5280x; 1.0087x over previous
#include <cuda_runtime.h>
#include <cstdint>

// ---------------------------------------------------------------------------
// MPS amplitude contraction, segment-table approach (v15).
// amplitude(s) = left[x0] . B[x1] ... B[x62] . right[x63]   (complex, D=16)
//
// Split: Lvec covers x0..x13 (14 bits), 6 x Seg6 cover x14..x49 (36 bits),
//        Rvec covers x50..x63 (14 bits).
// v15 = v14 with higher-MLP pack (unroll 8, hoisted load pairs).
//      Pipeline: kA'(pack blocks 0..255 || seg blocks 256..319) -> kB(256)
//      -> k_main (R9-proven 512-thread hot loop).
// ---------------------------------------------------------------------------

typedef unsigned long long ull;

__device__ float2 g_seg [64 * 256];
__device__ float2 g_lv8 [256 * 16];
__device__ float2 g_rv8 [256 * 16];
__device__ float2 g_lvec[16384 * 16];
__device__ float2 g_rvec[16384 * 16];
__device__ ull    g_xpack[131072];

// ---- packed fp32x2 helpers ----
__device__ __forceinline__ ull pack2(float lo, float hi) {
    ull r; asm("mov.b64 %0, {%1,%2};" : "=l"(r) : "f"(lo), "f"(hi)); return r;
}
__device__ __forceinline__ void unpack2(ull v, float& lo, float& hi) {
    asm("mov.b64 {%0,%1}, %2;" : "=f"(lo), "=f"(hi) : "l"(v));
}
__device__ __forceinline__ ull ffma2(ull a, ull b, ull c) {
    ull d; asm("fma.rn.f32x2 %0, %1, %2, %3;" : "=l"(d) : "l"(a), "l"(b), "l"(c));
    return d;
}
__device__ __forceinline__ void lds128(unsigned addr, ull& p0, ull& p1) {
    asm volatile("ld.shared.v2.b64 {%0,%1}, [%2];" : "=l"(p0), "=l"(p1) : "r"(addr));
}
__device__ __forceinline__ void sts128(unsigned addr, ull p0, ull p1) {
    asm volatile("st.shared.v2.b64 [%0], {%1,%2};" :: "r"(addr), "l"(p0), "l"(p1));
}
__device__ __forceinline__ void ldg128(const void* p, ull& p0, ull& p1) {
    asm volatile("ld.global.nc.v2.b64 {%0,%1}, [%2];" : "=l"(p0), "=l"(p1) : "l"(p));
}

// scalar complex fma: (rr,ri) += (ax+i ay) * (bx+i by)
__device__ __forceinline__ void cfma(float& rr, float& ri, float ax, float ay,
                                     float bx, float by) {
    rr = fmaf(ax, bx, rr);
    rr = fmaf(-ay, by, rr);
    ri = fmaf(ax, by, ri);
    ri = fmaf(ay, bx, ri);
}

// 16x16 complex matmul, one output element per thread (e = i*16+k, 256 thr)
__device__ __forceinline__ void mm16(const float2* A, const float2* Bm,
                                     float2* C, int e) {
    int i = e >> 4, k = e & 15;
    float xr0 = 0.f, xi0 = 0.f, xr1 = 0.f, xi1 = 0.f;
#pragma unroll
    for (int j = 0; j < 16; j += 2) {
        float2 a0 = A[(i << 4) + j],     b0 = Bm[(j << 4) + k];
        float2 a1 = A[(i << 4) + j + 1], b1 = Bm[((j + 1) << 4) + k];
        cfma(xr0, xi0, a0.x, a0.y, b0.x, b0.y);
        cfma(xr1, xi1, a1.x, a1.y, b1.x, b1.y);
    }
    C[e] = make_float2(xr0 + xr1, xi0 + xi1);
}

// ---------------------------------------------------------------------------
// kA': 320 blocks x 512 threads.
// Blocks 0..255: pack 512 samples each (16 warps x 32 samples, warp-ballot).
//   packed bit (63-t) = x_t. v15: 8-step batches — 16 loads issued up-front
//   per batch (MLP 16/warp), then ballots consume them.
// Blocks 256..319: block c-256 builds Seg6[c] (parallel Seg3 trees on
//   thread-halves) + Lv2/Rv2 -> Lv8/Rv8 slices.
// ---------------------------------------------------------------------------
__global__ __launch_bounds__(512) void kA(
        const int* __restrict__ x, int N,
        const float* __restrict__ br_, const float* __restrict__ bi_,
        const float* __restrict__ lr_, const float* __restrict__ li_,
        const float* __restrict__ rr_, const float* __restrict__ ri_) {
    if (blockIdx.x < 256) {
        int W = (blockIdx.x << 4) + (threadIdx.x >> 5);
        int lane = threadIdx.x & 31;
        int s0 = W << 5;
        if (s0 >= N) return;
        ull mine = 0;
#pragma unroll
        for (int qb = 0; qb < 32; qb += 8) {
            int v0[8], v1[8];
#pragma unroll
            for (int j = 0; j < 8; j++) {           // 16 loads in flight
                size_t base = (size_t)(s0 + qb + j) << 6;
                v0[j] = __ldg(x + base + lane);
                v1[j] = __ldg(x + base + 32 + lane);
            }
#pragma unroll
            for (int j = 0; j < 8; j++) {
                unsigned b0 = __ballot_sync(0xFFFFFFFFu, v0[j] & 1);
                unsigned b1 = __ballot_sync(0xFFFFFFFFu, v1[j] & 1);
                ull packed = ((ull)__brev(b0) << 32) | (ull)__brev(b1);
                if (lane == qb + j) mine = packed;
            }
        }
        if (s0 + lane < N) g_xpack[s0 + lane] = mine;
        return;
    }

    // ---- Seg6 builder blocks ----
    __shared__ float2 sB[512], sT[2][256], sP[2][256], sS6[256];
    __shared__ float2 sLv2[64], sRv2[64];
    __shared__ float sLr[32], sLi[32], sRr[32], sRi[32];
    int e = threadIdx.x, c = blockIdx.x - 256;
    int half = e >> 8, e2 = e & 255;

    sB[e] = make_float2(br_[e], bi_[e]);
    if (e < 32) { sLr[e] = lr_[e]; sLi[e] = li_[e]; sRr[e] = rr_[e]; sRi[e] = ri_[e]; }
    __syncthreads();

    int a = c >> 3, b = c & 7;
    int v = half ? b : a;
    mm16(sB + (((v >> 1) & 1) << 8), sB + ((v & 1) << 8), sT[half], e2);
    __syncthreads();
    mm16(sB + ((v >> 2) << 8), sT[half], sP[half], e2);
    __syncthreads();
    if (half == 0) mm16(sP[0], sP[1], sS6, e2);     // Seg6[c] = Seg3[a].Seg3[b]
    __syncthreads();

    if (half == 0) g_seg[(c << 8) + e2] = sS6[e2];

    if (e < 64) {  // Lv2[(s<<1)|bb][k] = sum_j left[s][j] * B[bb][j][k]
        int vv = e >> 4, k = e & 15, s = vv >> 1, bb = vv & 1;
        float xr = 0.f, xi = 0.f;
#pragma unroll
        for (int j = 0; j < 16; j++) {
            float2 m = sB[(bb << 8) + (j << 4) + k];
            cfma(xr, xi, sLr[s * 16 + j], sLi[s * 16 + j], m.x, m.y);
        }
        sLv2[e] = make_float2(xr, xi);
    } else if (e < 128) {  // Rv2[(bb<<1)|r][i] = sum_j B[bb][i][j] * right[r][j]
        int t2 = e - 64, vv = t2 >> 4, i = t2 & 15, bb = vv >> 1, r = vv & 1;
        float xr = 0.f, xi = 0.f;
#pragma unroll
        for (int j = 0; j < 16; j++) {
            float2 m = sB[(bb << 8) + (i << 4) + j];
            cfma(xr, xi, m.x, m.y, sRr[r * 16 + j], sRi[r * 16 + j]);
        }
        sRv2[t2] = make_float2(xr, xi);
    }
    __syncthreads();

    if (e < 64) {  // Lv8[(a2<<6)|c][k] = sum_j Lv2[a2][j] * Seg6[c][j][k]
        int a2 = e >> 4, k = e & 15;
        float xr = 0.f, xi = 0.f;
#pragma unroll
        for (int j = 0; j < 16; j++) {
            float2 o = sLv2[(a2 << 4) + j];
            float2 m = sS6[(j << 4) + k];
            cfma(xr, xi, o.x, o.y, m.x, m.y);
        }
        g_lv8[(((a2 << 6) | c) << 4) + k] = make_float2(xr, xi);
    } else if (e < 128) {  // Rv8[(c<<2)|b2][i] = sum_j Seg6[c][i][j] * Rv2[b2][j]
        int t2 = e - 64, b2 = t2 >> 4, i = t2 & 15;
        float xr = 0.f, xi = 0.f;
#pragma unroll
        for (int j = 0; j < 16; j++) {
            float2 m = sS6[(i << 4) + j];
            float2 w = sRv2[(b2 << 4) + j];
            cfma(xr, xi, m.x, m.y, w.x, w.y);
        }
        g_rv8[(((c << 2) | b2) << 4) + i] = make_float2(xr, xi);
    }
}

// ---------------------------------------------------------------------------
// kB: 256 blocks x 256 threads. Table expansion with dual-acc ILP, p-split.
// Blocks 0..127:  L side, c = blk>>1, p-half = blk&1.
// Blocks 128..255: R side, c = (blk-128)>>1, p-half = (blk-128)&1.
// ---------------------------------------------------------------------------
__global__ void kB() {
    __shared__ float2 S[256];
    int blk = blockIdx.x;
    int t = threadIdx.x;

    if (blk < 128) {
        int c = blk >> 1, ph = blk & 1;
        S[t] = g_seg[(c << 8) + t];           // S[j*16+k] = Seg6[c][j][k]
        __syncthreads();
        int k = t & 15, a8l = t >> 4;
#pragma unroll 1
        for (int p = ph * 8; p < ph * 8 + 8; p++) {
            int a8 = (p << 4) | a8l;
            const float2* w = g_lv8 + (a8 << 4);
            float xr0 = 0.f, xi0 = 0.f, xr1 = 0.f, xi1 = 0.f;
#pragma unroll
            for (int j = 0; j < 16; j += 2) {
                float2 o0 = __ldg(&w[j]),     b0 = S[(j << 4) + k];
                float2 o1 = __ldg(&w[j + 1]), b1 = S[((j + 1) << 4) + k];
                cfma(xr0, xi0, o0.x, o0.y, b0.x, b0.y);
                cfma(xr1, xi1, o1.x, o1.y, b1.x, b1.y);
            }
            g_lvec[(((a8 << 6) | c) << 4) + k] = make_float2(xr0 + xr1, xi0 + xi1);
        }
    } else {
        int b2 = blk - 128;
        int c = b2 >> 1, ph = b2 & 1;
        {
            int i = t >> 4, j = t & 15;
            S[(j << 4) | i] = g_seg[(c << 8) + t];  // transposed stage
        }
        __syncthreads();
        int il = t & 15, b8l = t >> 4;
#pragma unroll 1
        for (int p = ph * 8; p < ph * 8 + 8; p++) {
            int b8 = (p << 4) | b8l;
            const float2* w = g_rv8 + (b8 << 4);
            float xr0 = 0.f, xi0 = 0.f, xr1 = 0.f, xi1 = 0.f;
#pragma unroll
            for (int j = 0; j < 16; j += 2) {
                float2 w0 = __ldg(&w[j]),     b0 = S[(j << 4) + il];
                float2 w1 = __ldg(&w[j + 1]), b1 = S[((j + 1) << 4) + il];
                cfma(xr0, xi0, b0.x, b0.y, w0.x, w0.y);
                cfma(xr1, xi1, b1.x, b1.y, w1.x, w1.y);
            }
            g_rvec[(((c << 8) | b8) << 4) + il] = make_float2(xr0 + xr1, xi0 + xi1);
        }
    }
}

// ---------------------------------------------------------------------------
// Main kernel (R9-proven). 512 threads, one per sample, balanced contiguous
// chunk per block, warp-uniform outer loop. Smem: 128 KB Seg6 table + 64 KB
// gather staging. Lvec/Rvec fetched warp-cooperatively and staged; table
// column pairs read in lane-rotated order (deterministic 4-phase LDS.128).
// Register pair u of the state holds logical pair (u+rot)&7 after the
// first matvec.
// ---------------------------------------------------------------------------
__global__ __launch_bounds__(512) void k_main(float* __restrict__ out, int N) {
    extern __shared__ float2 smem_all[];
    float2* sSeg = smem_all;                    // 16384 float2 = 128 KB

    {
        const float4* src = reinterpret_cast<const float4*>(g_seg);
        float4* dst = reinterpret_cast<float4*>(sSeg);
        for (int e = threadIdx.x; e < 64 * 128; e += blockDim.x) dst[e] = src[e];
    }
    __syncthreads();

    unsigned sb;
    asm("{ .reg .u64 t; cvta.to.shared.u64 t, %1; cvt.u32.u64 %0, t; }"
        : "=r"(sb) : "l"(smem_all));
    const unsigned stgb   = sb + 131072u;            // staging base (bytes)
    const unsigned lane   = threadIdx.x & 31u;
    const unsigned rot    = threadIdx.x & 7u;
    const unsigned rot16  = rot << 4;
    const unsigned rot256 = rot << 8;
    const unsigned myStg  = stgb + ((unsigned)threadIdx.x << 7);
    const unsigned warpStg = stgb + ((unsigned)(threadIdx.x & ~31u) << 7);
    const int sub    = (int)(lane >> 3);             // 0..3
    const int chunku = (int)(lane & 7);              // 16B chunk this lane moves

    int chunk = (N + gridDim.x - 1) / gridDim.x;
    int start = blockIdx.x * chunk;
    int end = min(start + chunk, N);

    for (int base = start + (int)((threadIdx.x >> 5) << 5); base < end;
         base += (int)blockDim.x) {
        int s = base + (int)lane;
        bool active = s < end;
        ull packed = active ? __ldg(&g_xpack[s]) : 0ull;
        unsigned idxl = (unsigned)(packed >> 50);         // x0..x13
        unsigned idxr = (unsigned)packed & 0x3FFFu;       // x50..x63
        ull sp = packed << 14;                            // x14 at bit 63

        // ---- staged Lvec gather (slots swizzled by owner&7) ----
#pragma unroll
        for (int g = 0; g < 8; g++) {
            int owner = (g << 2) + sub;
            unsigned oidx = __shfl_sync(0xFFFFFFFFu, idxl, owner);
            const char* p = (const char*)g_lvec + ((size_t)oidx << 7) + (chunku << 4);
            ull a, b; ldg128(p, a, b);
            unsigned slot = (unsigned)(chunku ^ (owner & 7));
            sts128(warpStg + ((unsigned)owner << 7) + (slot << 4), a, b);
        }
        __syncwarp();

        float mr[16], mi[16];
#pragma unroll
        for (int u = 0; u < 8; u++) {                    // logical order
            unsigned slot = (unsigned)u ^ rot;
            ull a, b; lds128(myStg + (slot << 4), a, b);
            unpack2(a, mr[2 * u],     mi[2 * u]);
            unpack2(b, mr[2 * u + 1], mi[2 * u + 1]);
        }
        __syncwarp();   // all reads done before staging is reused below

        // ---- matvec 1: m in logical order, rows by immediate offsets ----
        {
            unsigned idx = (unsigned)(sp >> 58);
            sp <<= 6;
            unsigned mb = sb + (idx << 11);
            ull P[16], Q[16];
#pragma unroll
            for (int e = 0; e < 16; e++) { P[e] = 0ull; Q[e] = 0ull; }
            unsigned pu[8];
#pragma unroll
            for (int u = 0; u < 8; u++) pu[u] = mb + ((rot16 + (u << 4)) & 127u);
#pragma unroll
            for (int i = 0; i < 16; i++) {
                float ar = mr[i], ai = mi[i];
                ull arr = pack2(ar, ar), ai2 = pack2(ai, -ai);
#pragma unroll
                for (int u = 0; u < 8; u++) {
                    ull b0, b1;
                    lds128(pu[u] + (unsigned)(i << 7), b0, b1);
                    P[2 * u]     = ffma2(arr, b0, P[2 * u]);
                    Q[2 * u]     = ffma2(ai2, b0, Q[2 * u]);
                    P[2 * u + 1] = ffma2(arr, b1, P[2 * u + 1]);
                    Q[2 * u + 1] = ffma2(ai2, b1, Q[2 * u + 1]);
                }
            }
#pragma unroll
            for (int e = 0; e < 16; e++) {
                float pl, ph, ql, qh;
                unpack2(P[e], pl, ph);
                unpack2(Q[e], ql, qh);
                mr[e] = pl + qh;   // nr = ar*bx - ai*by
                mi[e] = ph + ql;   // ni = ar*by + ai*bx
            }
        }

        // ---- matvecs 2..6: state pair u holds logical pair (u+rot)&7 ----
#pragma unroll 1
        for (int kseg = 1; kseg < 6; kseg++) {
            unsigned idx = (unsigned)(sp >> 58);
            sp <<= 6;
            unsigned mb = sb + (idx << 11);
            ull P[16], Q[16];
#pragma unroll
            for (int e = 0; e < 16; e++) { P[e] = 0ull; Q[e] = 0ull; }
            unsigned pu[8];
#pragma unroll
            for (int u = 0; u < 8; u++) pu[u] = mb + ((rot16 + (u << 4)) & 127u);
#pragma unroll
            for (int spn = 0; spn < 8; spn++) {
                unsigned row = (rot256 + (unsigned)(spn << 8)) & 2047u;
#pragma unroll
                for (int hf = 0; hf < 2; hf++) {
                    float ar = mr[2 * spn + hf], ai = mi[2 * spn + hf];
                    ull arr = pack2(ar, ar), ai2 = pack2(ai, -ai);
#pragma unroll
                    for (int u = 0; u < 8; u++) {
                        ull b0, b1;
                        lds128(pu[u] + row + (unsigned)(hf << 7), b0, b1);
                        P[2 * u]     = ffma2(arr, b0, P[2 * u]);
                        Q[2 * u]     = ffma2(ai2, b0, Q[2 * u]);
                        P[2 * u + 1] = ffma2(arr, b1, P[2 * u + 1]);
                        Q[2 * u + 1] = ffma2(ai2, b1, Q[2 * u + 1]);
                    }
                }
            }
#pragma unroll
            for (int e = 0; e < 16; e++) {
                float pl, ph, ql, qh;
                unpack2(P[e], pl, ph);
                unpack2(Q[e], ql, qh);
                mr[e] = pl + qh;
                mi[e] = ph + ql;
            }
        }

        // ---- staged Rvec gather (unswizzled slots; read order is rotated) ----
#pragma unroll
        for (int g = 0; g < 8; g++) {
            int owner = (g << 2) + sub;
            unsigned oidx = __shfl_sync(0xFFFFFFFFu, idxr, owner);
            const char* p = (const char*)g_rvec + ((size_t)oidx << 7) + (chunku << 4);
            ull a, b; ldg128(p, a, b);
            sts128(warpStg + ((unsigned)owner << 7) + ((unsigned)chunku << 4), a, b);
        }
        __syncwarp();

        float accr = 0.f, acci = 0.f;
#pragma unroll
        for (int u = 0; u < 8; u++) {
            unsigned lp = (u + rot) & 7u;               // logical pair at step u
            ull a, b; lds128(myStg + (lp << 4), a, b);
            float c0x, c0y, c1x, c1y;
            unpack2(a, c0x, c0y);
            unpack2(b, c1x, c1y);
            int e0 = 2 * u, e1 = 2 * u + 1;
            accr = fmaf(mr[e0], c0x, accr);  accr = fmaf(-mi[e0], c0y, accr);
            acci = fmaf(mr[e0], c0y, acci);  acci = fmaf(mi[e0], c0x, acci);
            accr = fmaf(mr[e1], c1x, accr);  accr = fmaf(-mi[e1], c1y, accr);
            acci = fmaf(mr[e1], c1y, acci);  acci = fmaf(mi[e1], c1x, acci);
        }
        __syncwarp();   // staging reused next iteration

        if (active) {
            out[s]     = accr;
            out[N + s] = acci;
        }
    }
}

// ---------------------------------------------------------------------------
// kernel_launch
// inputs (metadata order): x, left_r, left_i, bulk_r, bulk_i, right_r, right_i
// out: float32, [2, N] flattened (re then im)
// ---------------------------------------------------------------------------
extern "C" void kernel_launch(void* const* d_in, const int* in_sizes, int n_in,
                              void* d_out, int out_size) {
    const int*   x       = (const int*)d_in[0];
    const float* left_r  = (const float*)d_in[1];
    const float* left_i  = (const float*)d_in[2];
    const float* bulk_r  = (const float*)d_in[3];
    const float* bulk_i  = (const float*)d_in[4];
    const float* right_r = (const float*)d_in[5];
    const float* right_i = (const float*)d_in[6];
    float* out = (float*)d_out;

    int N = in_sizes[0] / 64;

    static const size_t kSmem = 192 * 1024;  // 128 KB table + 64 KB staging
    cudaFuncSetAttribute(k_main, cudaFuncAttributeMaxDynamicSharedMemorySize,
                         (int)kSmem);

    kA<<<320, 512>>>(x, N, bulk_r, bulk_i, left_r, left_i, right_r, right_i);
    kB<<<256, 256>>>();
    k_main<<<148, 512, kSmem>>>(out, N);
}

// round 17
// speedup vs baseline: 1.5293x; 1.0009x over previous
#include <cuda_runtime.h>
#include <cstdint>

// ---------------------------------------------------------------------------
// MPS amplitude contraction, segment-table approach (v16).
// amplitude(s) = left[x0] . B[x1] ... B[x62] . right[x63]   (complex, D=16)
//
// Split: Lvec covers x0..x13 (14 bits), 6 x Seg6 cover x14..x49 (36 bits),
//        Rvec covers x50..x63 (14 bits).
// v16: pack moved from kA into kB as a parallel block range, overlapping
//      its DRAM time with table expansion (g_xpack is consumed only by
//      k_main). Pipeline: kA(64 builders) -> kB(256 expansion + 512 pack)
//      -> k_main (R9-proven 512-thread hot loop).
// ---------------------------------------------------------------------------

typedef unsigned long long ull;

__device__ float2 g_seg [64 * 256];
__device__ float2 g_lv8 [256 * 16];
__device__ float2 g_rv8 [256 * 16];
__device__ float2 g_lvec[16384 * 16];
__device__ float2 g_rvec[16384 * 16];
__device__ ull    g_xpack[131072];

// ---- packed fp32x2 helpers ----
__device__ __forceinline__ ull pack2(float lo, float hi) {
    ull r; asm("mov.b64 %0, {%1,%2};" : "=l"(r) : "f"(lo), "f"(hi)); return r;
}
__device__ __forceinline__ void unpack2(ull v, float& lo, float& hi) {
    asm("mov.b64 {%0,%1}, %2;" : "=f"(lo), "=f"(hi) : "l"(v));
}
__device__ __forceinline__ ull ffma2(ull a, ull b, ull c) {
    ull d; asm("fma.rn.f32x2 %0, %1, %2, %3;" : "=l"(d) : "l"(a), "l"(b), "l"(c));
    return d;
}
__device__ __forceinline__ void lds128(unsigned addr, ull& p0, ull& p1) {
    asm volatile("ld.shared.v2.b64 {%0,%1}, [%2];" : "=l"(p0), "=l"(p1) : "r"(addr));
}
__device__ __forceinline__ void sts128(unsigned addr, ull p0, ull p1) {
    asm volatile("st.shared.v2.b64 [%0], {%1,%2};" :: "r"(addr), "l"(p0), "l"(p1));
}
__device__ __forceinline__ void ldg128(const void* p, ull& p0, ull& p1) {
    asm volatile("ld.global.nc.v2.b64 {%0,%1}, [%2];" : "=l"(p0), "=l"(p1) : "l"(p));
}

// scalar complex fma: (rr,ri) += (ax+i ay) * (bx+i by)
__device__ __forceinline__ void cfma(float& rr, float& ri, float ax, float ay,
                                     float bx, float by) {
    rr = fmaf(ax, bx, rr);
    rr = fmaf(-ay, by, rr);
    ri = fmaf(ax, by, ri);
    ri = fmaf(ay, bx, ri);
}

// 16x16 complex matmul, one output element per thread (e = i*16+k, 256 thr)
__device__ __forceinline__ void mm16(const float2* A, const float2* Bm,
                                     float2* C, int e) {
    int i = e >> 4, k = e & 15;
    float xr0 = 0.f, xi0 = 0.f, xr1 = 0.f, xi1 = 0.f;
#pragma unroll
    for (int j = 0; j < 16; j += 2) {
        float2 a0 = A[(i << 4) + j],     b0 = Bm[(j << 4) + k];
        float2 a1 = A[(i << 4) + j + 1], b1 = Bm[((j + 1) << 4) + k];
        cfma(xr0, xi0, a0.x, a0.y, b0.x, b0.y);
        cfma(xr1, xi1, a1.x, a1.y, b1.x, b1.y);
    }
    C[e] = make_float2(xr0 + xr1, xi0 + xi1);
}

// ---------------------------------------------------------------------------
// kA: 64 blocks x 512 threads. Block c builds Seg6[c] (parallel Seg3 trees
// on thread-halves) + Lv2/Rv2 -> Lv8/Rv8 slices.
// ---------------------------------------------------------------------------
__global__ __launch_bounds__(512) void kA(
        const float* __restrict__ br_, const float* __restrict__ bi_,
        const float* __restrict__ lr_, const float* __restrict__ li_,
        const float* __restrict__ rr_, const float* __restrict__ ri_) {
    __shared__ float2 sB[512], sT[2][256], sP[2][256], sS6[256];
    __shared__ float2 sLv2[64], sRv2[64];
    __shared__ float sLr[32], sLi[32], sRr[32], sRi[32];
    int e = threadIdx.x, c = blockIdx.x;
    int half = e >> 8, e2 = e & 255;

    sB[e] = make_float2(br_[e], bi_[e]);
    if (e < 32) { sLr[e] = lr_[e]; sLi[e] = li_[e]; sRr[e] = rr_[e]; sRi[e] = ri_[e]; }
    __syncthreads();

    int a = c >> 3, b = c & 7;
    int v = half ? b : a;
    mm16(sB + (((v >> 1) & 1) << 8), sB + ((v & 1) << 8), sT[half], e2);
    __syncthreads();
    mm16(sB + ((v >> 2) << 8), sT[half], sP[half], e2);
    __syncthreads();
    if (half == 0) mm16(sP[0], sP[1], sS6, e2);     // Seg6[c] = Seg3[a].Seg3[b]
    __syncthreads();

    if (half == 0) g_seg[(c << 8) + e2] = sS6[e2];

    if (e < 64) {  // Lv2[(s<<1)|bb][k] = sum_j left[s][j] * B[bb][j][k]
        int vv = e >> 4, k = e & 15, s = vv >> 1, bb = vv & 1;
        float xr = 0.f, xi = 0.f;
#pragma unroll
        for (int j = 0; j < 16; j++) {
            float2 m = sB[(bb << 8) + (j << 4) + k];
            cfma(xr, xi, sLr[s * 16 + j], sLi[s * 16 + j], m.x, m.y);
        }
        sLv2[e] = make_float2(xr, xi);
    } else if (e < 128) {  // Rv2[(bb<<1)|r][i] = sum_j B[bb][i][j] * right[r][j]
        int t2 = e - 64, vv = t2 >> 4, i = t2 & 15, bb = vv >> 1, r = vv & 1;
        float xr = 0.f, xi = 0.f;
#pragma unroll
        for (int j = 0; j < 16; j++) {
            float2 m = sB[(bb << 8) + (i << 4) + j];
            cfma(xr, xi, m.x, m.y, sRr[r * 16 + j], sRi[r * 16 + j]);
        }
        sRv2[t2] = make_float2(xr, xi);
    }
    __syncthreads();

    if (e < 64) {  // Lv8[(a2<<6)|c][k] = sum_j Lv2[a2][j] * Seg6[c][j][k]
        int a2 = e >> 4, k = e & 15;
        float xr = 0.f, xi = 0.f;
#pragma unroll
        for (int j = 0; j < 16; j++) {
            float2 o = sLv2[(a2 << 4) + j];
            float2 m = sS6[(j << 4) + k];
            cfma(xr, xi, o.x, o.y, m.x, m.y);
        }
        g_lv8[(((a2 << 6) | c) << 4) + k] = make_float2(xr, xi);
    } else if (e < 128) {  // Rv8[(c<<2)|b2][i] = sum_j Seg6[c][i][j] * Rv2[b2][j]
        int t2 = e - 64, b2 = t2 >> 4, i = t2 & 15;
        float xr = 0.f, xi = 0.f;
#pragma unroll
        for (int j = 0; j < 16; j++) {
            float2 m = sS6[(i << 4) + j];
            float2 w = sRv2[(b2 << 4) + j];
            cfma(xr, xi, m.x, m.y, w.x, w.y);
        }
        g_rv8[(((c << 2) | b2) << 4) + i] = make_float2(xr, xi);
    }
}

// ---------------------------------------------------------------------------
// kB: 768 blocks x 256 threads.
// Blocks 0..127:  L expansion, c = blk>>1, p-half = blk&1.
// Blocks 128..255: R expansion, c = (blk-128)>>1, p-half = (blk-128)&1.
// Blocks 256..767: pack — 512 blocks x 8 warps x 32 samples = 131072.
//   packed bit (63-t) = x_t; overlaps DRAM time with expansion compute.
// ---------------------------------------------------------------------------
__global__ void kB(const int* __restrict__ x, int N) {
    __shared__ float2 S[256];
    int blk = blockIdx.x;
    int t = threadIdx.x;

    if (blk >= 256) {
        // ---- pack blocks ----
        int W = ((blk - 256) << 3) + (t >> 5);
        int lane = t & 31;
        int s0 = W << 5;
        if (s0 >= N) return;
        ull mine = 0;
#pragma unroll
        for (int qb = 0; qb < 32; qb += 8) {
            int v0[8], v1[8];
#pragma unroll
            for (int j = 0; j < 8; j++) {
                size_t base = (size_t)(s0 + qb + j) << 6;
                v0[j] = __ldg(x + base + lane);
                v1[j] = __ldg(x + base + 32 + lane);
            }
#pragma unroll
            for (int j = 0; j < 8; j++) {
                unsigned b0 = __ballot_sync(0xFFFFFFFFu, v0[j] & 1);
                unsigned b1 = __ballot_sync(0xFFFFFFFFu, v1[j] & 1);
                ull packed = ((ull)__brev(b0) << 32) | (ull)__brev(b1);
                if (lane == qb + j) mine = packed;
            }
        }
        if (s0 + lane < N) g_xpack[s0 + lane] = mine;
        return;
    }

    if (blk < 128) {
        int c = blk >> 1, ph = blk & 1;
        S[t] = g_seg[(c << 8) + t];           // S[j*16+k] = Seg6[c][j][k]
        __syncthreads();
        int k = t & 15, a8l = t >> 4;
#pragma unroll 1
        for (int p = ph * 8; p < ph * 8 + 8; p++) {
            int a8 = (p << 4) | a8l;
            const float2* w = g_lv8 + (a8 << 4);
            float xr0 = 0.f, xi0 = 0.f, xr1 = 0.f, xi1 = 0.f;
#pragma unroll
            for (int j = 0; j < 16; j += 2) {
                float2 o0 = __ldg(&w[j]),     b0 = S[(j << 4) + k];
                float2 o1 = __ldg(&w[j + 1]), b1 = S[((j + 1) << 4) + k];
                cfma(xr0, xi0, o0.x, o0.y, b0.x, b0.y);
                cfma(xr1, xi1, o1.x, o1.y, b1.x, b1.y);
            }
            g_lvec[(((a8 << 6) | c) << 4) + k] = make_float2(xr0 + xr1, xi0 + xi1);
        }
    } else {
        int b2 = blk - 128;
        int c = b2 >> 1, ph = b2 & 1;
        {
            int i = t >> 4, j = t & 15;
            S[(j << 4) | i] = g_seg[(c << 8) + t];  // transposed stage
        }
        __syncthreads();
        int il = t & 15, b8l = t >> 4;
#pragma unroll 1
        for (int p = ph * 8; p < ph * 8 + 8; p++) {
            int b8 = (p << 4) | b8l;
            const float2* w = g_rv8 + (b8 << 4);
            float xr0 = 0.f, xi0 = 0.f, xr1 = 0.f, xi1 = 0.f;
#pragma unroll
            for (int j = 0; j < 16; j += 2) {
                float2 w0 = __ldg(&w[j]),     b0 = S[(j << 4) + il];
                float2 w1 = __ldg(&w[j + 1]), b1 = S[((j + 1) << 4) + il];
                cfma(xr0, xi0, b0.x, b0.y, w0.x, w0.y);
                cfma(xr1, xi1, b1.x, b1.y, w1.x, w1.y);
            }
            g_rvec[(((c << 8) | b8) << 4) + il] = make_float2(xr0 + xr1, xi0 + xi1);
        }
    }
}

// ---------------------------------------------------------------------------
// Main kernel (R9-proven). 512 threads, one per sample, balanced contiguous
// chunk per block, warp-uniform outer loop. Smem: 128 KB Seg6 table + 64 KB
// gather staging. Lvec/Rvec fetched warp-cooperatively and staged; table
// column pairs read in lane-rotated order (deterministic 4-phase LDS.128).
// Register pair u of the state holds logical pair (u+rot)&7 after the
// first matvec.
// ---------------------------------------------------------------------------
__global__ __launch_bounds__(512) void k_main(float* __restrict__ out, int N) {
    extern __shared__ float2 smem_all[];
    float2* sSeg = smem_all;                    // 16384 float2 = 128 KB

    {
        const float4* src = reinterpret_cast<const float4*>(g_seg);
        float4* dst = reinterpret_cast<float4*>(sSeg);
        for (int e = threadIdx.x; e < 64 * 128; e += blockDim.x) dst[e] = src[e];
    }
    __syncthreads();

    unsigned sb;
    asm("{ .reg .u64 t; cvta.to.shared.u64 t, %1; cvt.u32.u64 %0, t; }"
        : "=r"(sb) : "l"(smem_all));
    const unsigned stgb   = sb + 131072u;            // staging base (bytes)
    const unsigned lane   = threadIdx.x & 31u;
    const unsigned rot    = threadIdx.x & 7u;
    const unsigned rot16  = rot << 4;
    const unsigned rot256 = rot << 8;
    const unsigned myStg  = stgb + ((unsigned)threadIdx.x << 7);
    const unsigned warpStg = stgb + ((unsigned)(threadIdx.x & ~31u) << 7);
    const int sub    = (int)(lane >> 3);             // 0..3
    const int chunku = (int)(lane & 7);              // 16B chunk this lane moves

    int chunk = (N + gridDim.x - 1) / gridDim.x;
    int start = blockIdx.x * chunk;
    int end = min(start + chunk, N);

    for (int base = start + (int)((threadIdx.x >> 5) << 5); base < end;
         base += (int)blockDim.x) {
        int s = base + (int)lane;
        bool active = s < end;
        ull packed = active ? __ldg(&g_xpack[s]) : 0ull;
        unsigned idxl = (unsigned)(packed >> 50);         // x0..x13
        unsigned idxr = (unsigned)packed & 0x3FFFu;       // x50..x63
        ull sp = packed << 14;                            // x14 at bit 63

        // ---- staged Lvec gather (slots swizzled by owner&7) ----
#pragma unroll
        for (int g = 0; g < 8; g++) {
            int owner = (g << 2) + sub;
            unsigned oidx = __shfl_sync(0xFFFFFFFFu, idxl, owner);
            const char* p = (const char*)g_lvec + ((size_t)oidx << 7) + (chunku << 4);
            ull a, b; ldg128(p, a, b);
            unsigned slot = (unsigned)(chunku ^ (owner & 7));
            sts128(warpStg + ((unsigned)owner << 7) + (slot << 4), a, b);
        }
        __syncwarp();

        float mr[16], mi[16];
#pragma unroll
        for (int u = 0; u < 8; u++) {                    // logical order
            unsigned slot = (unsigned)u ^ rot;
            ull a, b; lds128(myStg + (slot << 4), a, b);
            unpack2(a, mr[2 * u],     mi[2 * u]);
            unpack2(b, mr[2 * u + 1], mi[2 * u + 1]);
        }
        __syncwarp();   // all reads done before staging is reused below

        // ---- matvec 1: m in logical order, rows by immediate offsets ----
        {
            unsigned idx = (unsigned)(sp >> 58);
            sp <<= 6;
            unsigned mb = sb + (idx << 11);
            ull P[16], Q[16];
#pragma unroll
            for (int e = 0; e < 16; e++) { P[e] = 0ull; Q[e] = 0ull; }
            unsigned pu[8];
#pragma unroll
            for (int u = 0; u < 8; u++) pu[u] = mb + ((rot16 + (u << 4)) & 127u);
#pragma unroll
            for (int i = 0; i < 16; i++) {
                float ar = mr[i], ai = mi[i];
                ull arr = pack2(ar, ar), ai2 = pack2(ai, -ai);
#pragma unroll
                for (int u = 0; u < 8; u++) {
                    ull b0, b1;
                    lds128(pu[u] + (unsigned)(i << 7), b0, b1);
                    P[2 * u]     = ffma2(arr, b0, P[2 * u]);
                    Q[2 * u]     = ffma2(ai2, b0, Q[2 * u]);
                    P[2 * u + 1] = ffma2(arr, b1, P[2 * u + 1]);
                    Q[2 * u + 1] = ffma2(ai2, b1, Q[2 * u + 1]);
                }
            }
#pragma unroll
            for (int e = 0; e < 16; e++) {
                float pl, ph, ql, qh;
                unpack2(P[e], pl, ph);
                unpack2(Q[e], ql, qh);
                mr[e] = pl + qh;   // nr = ar*bx - ai*by
                mi[e] = ph + ql;   // ni = ar*by + ai*bx
            }
        }

        // ---- matvecs 2..6: state pair u holds logical pair (u+rot)&7 ----
#pragma unroll 1
        for (int kseg = 1; kseg < 6; kseg++) {
            unsigned idx = (unsigned)(sp >> 58);
            sp <<= 6;
            unsigned mb = sb + (idx << 11);
            ull P[16], Q[16];
#pragma unroll
            for (int e = 0; e < 16; e++) { P[e] = 0ull; Q[e] = 0ull; }
            unsigned pu[8];
#pragma unroll
            for (int u = 0; u < 8; u++) pu[u] = mb + ((rot16 + (u << 4)) & 127u);
#pragma unroll
            for (int spn = 0; spn < 8; spn++) {
                unsigned row = (rot256 + (unsigned)(spn << 8)) & 2047u;
#pragma unroll
                for (int hf = 0; hf < 2; hf++) {
                    float ar = mr[2 * spn + hf], ai = mi[2 * spn + hf];
                    ull arr = pack2(ar, ar), ai2 = pack2(ai, -ai);
#pragma unroll
                    for (int u = 0; u < 8; u++) {
                        ull b0, b1;
                        lds128(pu[u] + row + (unsigned)(hf << 7), b0, b1);
                        P[2 * u]     = ffma2(arr, b0, P[2 * u]);
                        Q[2 * u]     = ffma2(ai2, b0, Q[2 * u]);
                        P[2 * u + 1] = ffma2(arr, b1, P[2 * u + 1]);
                        Q[2 * u + 1] = ffma2(ai2, b1, Q[2 * u + 1]);
                    }
                }
            }
#pragma unroll
            for (int e = 0; e < 16; e++) {
                float pl, ph, ql, qh;
                unpack2(P[e], pl, ph);
                unpack2(Q[e], ql, qh);
                mr[e] = pl + qh;
                mi[e] = ph + ql;
            }
        }

        // ---- staged Rvec gather (unswizzled slots; read order is rotated) ----
#pragma unroll
        for (int g = 0; g < 8; g++) {
            int owner = (g << 2) + sub;
            unsigned oidx = __shfl_sync(0xFFFFFFFFu, idxr, owner);
            const char* p = (const char*)g_rvec + ((size_t)oidx << 7) + (chunku << 4);
            ull a, b; ldg128(p, a, b);
            sts128(warpStg + ((unsigned)owner << 7) + ((unsigned)chunku << 4), a, b);
        }
        __syncwarp();

        float accr = 0.f, acci = 0.f;
#pragma unroll
        for (int u = 0; u < 8; u++) {
            unsigned lp = (u + rot) & 7u;               // logical pair at step u
            ull a, b; lds128(myStg + (lp << 4), a, b);
            float c0x, c0y, c1x, c1y;
            unpack2(a, c0x, c0y);
            unpack2(b, c1x, c1y);
            int e0 = 2 * u, e1 = 2 * u + 1;
            accr = fmaf(mr[e0], c0x, accr);  accr = fmaf(-mi[e0], c0y, accr);
            acci = fmaf(mr[e0], c0y, acci);  acci = fmaf(mi[e0], c0x, acci);
            accr = fmaf(mr[e1], c1x, accr);  accr = fmaf(-mi[e1], c1y, accr);
            acci = fmaf(mr[e1], c1y, acci);  acci = fmaf(mi[e1], c1x, acci);
        }
        __syncwarp();   // staging reused next iteration

        if (active) {
            out[s]     = accr;
            out[N + s] = acci;
        }
    }
}

// ---------------------------------------------------------------------------
// kernel_launch
// inputs (metadata order): x, left_r, left_i, bulk_r, bulk_i, right_r, right_i
// out: float32, [2, N] flattened (re then im)
// ---------------------------------------------------------------------------
extern "C" void kernel_launch(void* const* d_in, const int* in_sizes, int n_in,
                              void* d_out, int out_size) {
    const int*   x       = (const int*)d_in[0];
    const float* left_r  = (const float*)d_in[1];
    const float* left_i  = (const float*)d_in[2];
    const float* bulk_r  = (const float*)d_in[3];
    const float* bulk_i  = (const float*)d_in[4];
    const float* right_r = (const float*)d_in[5];
    const float* right_i = (const float*)d_in[6];
    float* out = (float*)d_out;

    int N = in_sizes[0] / 64;

    static const size_t kSmem = 192 * 1024;  // 128 KB table + 64 KB staging
    cudaFuncSetAttribute(k_main, cudaFuncAttributeMaxDynamicSharedMemorySize,
                         (int)kSmem);

    kA<<<64, 512>>>(bulk_r, bulk_i, left_r, left_i, right_r, right_i);
    kB<<<768, 256>>>(x, N);
    k_main<<<148, 512, kSmem>>>(out, N);
}